// round 13
// baseline (speedup 1.0000x reference)
#include <cuda_runtime.h>
#include <cuda_bf16.h>
#include <math.h>
#include <stdint.h>

#define DIMN 2048
#define NHEADS 16
#define HDIM 128
#define BATCH 2
#define LQ 4096
#define LCTX 769
#define IMG_T 257
#define TXT_T 512
#define EPS_F 1e-6f
#define ATT_SCALE 0.08838834764831845f  /* 1/sqrt(128) */

// ---------------- scratch (device globals; no allocs allowed) --------------
__device__ float g_Q   [BATCH * LQ    * DIMN];
__device__ float g_Ktxt[BATCH * TXT_T * DIMN];
__device__ float g_Kimg[BATCH * IMG_T * DIMN];

// bf16 hi/lo split buffers
#define MPAD_IMG 640
__device__ __nv_bfloat16 g_xh [BATCH * LQ * DIMN];
__device__ __nv_bfloat16 g_xl [BATCH * LQ * DIMN];
__device__ __nv_bfloat16 g_ah [BATCH * LQ * DIMN];
__device__ __nv_bfloat16 g_al [BATCH * LQ * DIMN];
__device__ __nv_bfloat16 g_cth[BATCH * TXT_T * DIMN];
__device__ __nv_bfloat16 g_ctl[BATCH * TXT_T * DIMN];
__device__ __nv_bfloat16 g_cih[MPAD_IMG * DIMN];
__device__ __nv_bfloat16 g_cil[MPAD_IMG * DIMN];
__device__ __nv_bfloat16 g_wqh [DIMN * DIMN], g_wql [DIMN * DIMN];
__device__ __nv_bfloat16 g_wkh [DIMN * DIMN], g_wkl [DIMN * DIMN];
__device__ __nv_bfloat16 g_wvh [DIMN * DIMN], g_wvl [DIMN * DIMN];
__device__ __nv_bfloat16 g_wkih[DIMN * DIMN], g_wkil[DIMN * DIMN];
__device__ __nv_bfloat16 g_wvih[DIMN * DIMN], g_wvil[DIMN * DIMN];
__device__ __nv_bfloat16 g_woh [DIMN * DIMN], g_wol [DIMN * DIMN];

// attention-side hi/lo operands
__device__ __nv_bfloat16 g_Qh [BATCH * LQ * DIMN],    g_Ql [BATCH * LQ * DIMN];
__device__ __nv_bfloat16 g_Kth[BATCH * TXT_T * DIMN], g_Ktl[BATCH * TXT_T * DIMN];
__device__ __nv_bfloat16 g_Vth[BATCH * TXT_T * DIMN], g_Vtl[BATCH * TXT_T * DIMN];
__device__ __nv_bfloat16 g_Kih[BATCH * IMG_T * DIMN], g_Kil[BATCH * IMG_T * DIMN];
__device__ __nv_bfloat16 g_Vih[MPAD_IMG * DIMN],      g_Vil[MPAD_IMG * DIMN];

// ---------------------------- helpers ---------------------------------------
__device__ __forceinline__ uint32_t smem_u32(const void* p) {
    uint32_t a;
    asm("{ .reg .u64 t; cvta.to.shared.u64 t, %1; cvt.u32.u64 %0, t; }"
        : "=r"(a) : "l"(p));
    return a;
}

__device__ __forceinline__ void mma16816(float* d, const uint32_t* a,
                                         const uint32_t b0, const uint32_t b1) {
    asm volatile(
        "mma.sync.aligned.m16n8k16.row.col.f32.bf16.bf16.f32 "
        "{%0,%1,%2,%3}, {%4,%5,%6,%7}, {%8,%9}, {%0,%1,%2,%3};"
        : "+f"(d[0]), "+f"(d[1]), "+f"(d[2]), "+f"(d[3])
        : "r"(a[0]), "r"(a[1]), "r"(a[2]), "r"(a[3]), "r"(b0), "r"(b1));
}

__device__ __forceinline__ void ldsm4(uint32_t* r, uint32_t a) {
    asm volatile("ldmatrix.sync.aligned.m8n8.x4.shared.b16 {%0,%1,%2,%3}, [%4];"
                 : "=r"(r[0]), "=r"(r[1]), "=r"(r[2]), "=r"(r[3]) : "r"(a));
}
__device__ __forceinline__ void ldsm4t(uint32_t* r, uint32_t a) {
    asm volatile("ldmatrix.sync.aligned.m8n8.x4.trans.shared.b16 {%0,%1,%2,%3}, [%4];"
                 : "=r"(r[0]), "=r"(r[1]), "=r"(r[2]), "=r"(r[3]) : "r"(a));
}
__device__ __forceinline__ void cp16(uint32_t d, const void* s) {
    asm volatile("cp.async.cg.shared.global [%0], [%1], 16;"
                 :: "r"(d), "l"(s) : "memory");
}
__device__ __forceinline__ void cp16z(uint32_t d, const void* s, int sz) {
    asm volatile("cp.async.cg.shared.global [%0], [%1], 16, %2;"
                 :: "r"(d), "l"(s), "r"(sz) : "memory");
}
#define CP_COMMIT() asm volatile("cp.async.commit_group;" ::: "memory")
#define CP_WAIT(n)  asm volatile("cp.async.wait_group %0;" :: "n"(n) : "memory")

// f32x2 -> bf16x2 hi + lo residual
__device__ __forceinline__ void split2(float2 f, uint32_t& h, uint32_t& l) {
    __nv_bfloat162 hb = __float22bfloat162_rn(f);
    float2 hf = __bfloat1622float2(hb);
    __nv_bfloat162 lb = __float22bfloat162_rn(make_float2(f.x - hf.x, f.y - hf.y));
    h = *(uint32_t*)&hb;
    l = *(uint32_t*)&lb;
}

// -------------- batched fp32 -> bf16 hi/lo split (9 jobs, one launch) ------
struct CJob {
    const float* src;
    __nv_bfloat16 *hi, *lo;
    int Mvalid, rows_pb, bstride, roff, blk0;
};
struct CParams { CJob j[9]; };

__global__ __launch_bounds__(256)
void cvt_batch(CParams P)
{
    const int bid = blockIdx.x;
    int ji = 0;
#pragma unroll
    for (int k = 1; k < 9; k++) if (bid >= P.j[k].blk0) ji = k;
    const CJob& J = P.j[ji];

    const long e = (long)(bid - J.blk0) * 1024 + threadIdx.x * 4;
    const int m = (int)(e >> 11);
    const int col = (int)(e & 2047);

    float4 v = make_float4(0.f, 0.f, 0.f, 0.f);
    if (m < J.Mvalid) {
        const int bb = m / J.rows_pb;
        const long srow = (long)bb * J.bstride + J.roff + (m - bb * J.rows_pb);
        v = *(const float4*)(J.src + srow * DIMN + col);
    }
    uint32_t h0, l0, h1, l1;
    split2(make_float2(v.x, v.y), h0, l0);
    split2(make_float2(v.z, v.w), h1, l1);
    *(uint2*)(J.hi + e) = make_uint2(h0, h1);
    *(uint2*)(J.lo + e) = make_uint2(l0, l1);
}

// ------------- batched HMMA GEMM: C = (Ah+Al)(Bh+Bl)^T + bias (3 terms) ----
#define GT_KC 32
#define NCHUNK (DIMN / GT_KC)        /* 64 */
#define TILE_B   10240               /* 128 x 80 bytes */
#define BUF_B    (4 * TILE_B)
#define GEMM_SMEM (2 * BUF_B)

struct GJob {
    const __nv_bfloat16 *Ah, *Al, *Bh, *Bl;
    const float *bias;
    float *C;                      // fp32 out (may be null)
    __nv_bfloat16 *Ch, *Cl;        // hi/lo out (may be null)
    int Mvalid;
    int cta0;
};
struct GParams { GJob j[5]; };

__global__ __launch_bounds__(256, 2)
void gemm_batch(GParams P)
{
    extern __shared__ __nv_bfloat16 sm[];

    const int bid = blockIdx.x;
    int ji = 0;
#pragma unroll
    for (int k = 1; k < 5; k++) if (bid >= P.j[k].cta0) ji = k;
    const GJob& J = P.j[ji];
    const int local = bid - J.cta0;
    const int n0 = (local & 15) * 128;
    const int m0 = (local >> 4) * 128;

    const int tid = threadIdx.x;
    const int wid = tid >> 5;
    const int lane = tid & 31;
    const int wm = wid & 3;
    const int wn = wid >> 2;

    const __nv_bfloat16* srcs[4] = {
        J.Ah + (size_t)m0 * DIMN, J.Al + (size_t)m0 * DIMN,
        J.Bh + (size_t)n0 * DIMN, J.Bl + (size_t)n0 * DIMN };

    const uint32_t smb = smem_u32(sm);

    auto load_chunk = [&](int c, int b) {
        const int k0 = c * GT_KC;
#pragma unroll
        for (int j = 0; j < 8; j++) {
            const int f = j * 256 + tid;
            const int tile = f >> 9;
            const int w = f & 511;
            const int r = w >> 2;
            const int cc = w & 3;
            const __nv_bfloat16* sp = srcs[tile] + (size_t)r * DIMN + k0 + cc * 8;
            cp16(smb + b * BUF_B + tile * TILE_B + r * 80 + cc * 16, sp);
        }
        CP_COMMIT();
    };

    float acc[2][8][4];
#pragma unroll
    for (int i = 0; i < 2; i++)
#pragma unroll
        for (int j = 0; j < 8; j++)
#pragma unroll
            for (int q = 0; q < 4; q++) acc[i][j][q] = 0.f;

    const uint32_t aOff = (uint32_t)(wm * 32 + (lane & 15)) * 80 + ((lane >> 4) * 16);
    const uint32_t bOff = (uint32_t)(wn * 64 + (lane & 7) + ((lane >> 4) << 3)) * 80
                        + (((lane >> 3) & 1) * 16) + 2 * TILE_B;

    load_chunk(0, 0);
    load_chunk(1, 1);

    for (int c = 0; c < NCHUNK; c++) {
        const int b = c & 1;
        if (c == NCHUNK - 1) CP_WAIT(0);
        else                 CP_WAIT(1);
        __syncthreads();

        const uint32_t buf = smb + b * BUF_B;

#pragma unroll
        for (int s = 0; s < 2; s++) {
            uint32_t ah_[2][4], al_[2][4];
#pragma unroll
            for (int mt = 0; mt < 2; mt++) {
                ldsm4(ah_[mt], buf + aOff + mt * 16 * 80 + s * 32);
                ldsm4(al_[mt], buf + aOff + mt * 16 * 80 + s * 32 + TILE_B);
            }
#pragma unroll
            for (int t = 0; t < 4; t++) {
                uint32_t bh_[4], bl_[4];
                ldsm4(bh_, buf + bOff + t * 16 * 80 + s * 32);
                ldsm4(bl_, buf + bOff + t * 16 * 80 + s * 32 + TILE_B);
#pragma unroll
                for (int mt = 0; mt < 2; mt++) {
                    mma16816(acc[mt][2 * t],     ah_[mt], bh_[0], bh_[1]);
                    mma16816(acc[mt][2 * t],     ah_[mt], bl_[0], bl_[1]);
                    mma16816(acc[mt][2 * t],     al_[mt], bh_[0], bh_[1]);
                    mma16816(acc[mt][2 * t + 1], ah_[mt], bh_[2], bh_[3]);
                    mma16816(acc[mt][2 * t + 1], ah_[mt], bl_[2], bl_[3]);
                    mma16816(acc[mt][2 * t + 1], al_[mt], bh_[2], bh_[3]);
                }
            }
        }
        __syncthreads();
        if (c + 2 < NCHUNK) load_chunk(c + 2, b);
    }

    const int lr = lane >> 2;
    const int lc = (lane & 3) * 2;
#pragma unroll
    for (int mt = 0; mt < 2; mt++) {
#pragma unroll
        for (int nt = 0; nt < 8; nt++) {
            const int n = n0 + wn * 64 + nt * 8 + lc;
            const float2 bv = *(const float2*)&J.bias[n];
            const int mA = m0 + wm * 32 + mt * 16 + lr;
            float2 o0 = make_float2(acc[mt][nt][0] + bv.x, acc[mt][nt][1] + bv.y);
            float2 o1 = make_float2(acc[mt][nt][2] + bv.x, acc[mt][nt][3] + bv.y);
            if (J.C) {
                if (mA < J.Mvalid)     *(float2*)(J.C + (size_t)mA * DIMN + n) = o0;
                if (mA + 8 < J.Mvalid) *(float2*)(J.C + (size_t)(mA + 8) * DIMN + n) = o1;
            }
            if (J.Ch) {
                uint32_t hh, ll;
                if (mA < J.Mvalid) {
                    split2(o0, hh, ll);
                    *(uint32_t*)(J.Ch + (size_t)mA * DIMN + n) = hh;
                    *(uint32_t*)(J.Cl + (size_t)mA * DIMN + n) = ll;
                }
                if (mA + 8 < J.Mvalid) {
                    split2(o1, hh, ll);
                    *(uint32_t*)(J.Ch + (size_t)(mA + 8) * DIMN + n) = hh;
                    *(uint32_t*)(J.Cl + (size_t)(mA + 8) * DIMN + n) = ll;
                }
            }
        }
    }
}

// ------------- batched RMS norm -> bf16 hi/lo split (3 jobs) ---------------
struct RJob {
    const float* X;
    const float* g;
    __nv_bfloat16 *H, *L;
    int row0;
};
struct RParams { RJob j[3]; };

__global__ __launch_bounds__(256)
void rmsnorm_batch(RParams P)
{
    const int bid = blockIdx.x;
    int ji = 0;
#pragma unroll
    for (int k = 1; k < 3; k++) if (bid >= P.j[k].row0) ji = k;
    const RJob& J = P.j[ji];
    const int row = bid - J.row0;

    const float* xr = J.X + (long)row * DIMN;
    const int t = threadIdx.x;

    float4 v0 = *(const float4*)&xr[t * 4];
    float4 v1 = *(const float4*)&xr[1024 + t * 4];
    float ss = v0.x * v0.x + v0.y * v0.y + v0.z * v0.z + v0.w * v0.w
             + v1.x * v1.x + v1.y * v1.y + v1.z * v1.z + v1.w * v1.w;

#pragma unroll
    for (int o = 16; o > 0; o >>= 1) ss += __shfl_xor_sync(0xffffffffu, ss, o);

    __shared__ float red[8];
    if ((t & 31) == 0) red[t >> 5] = ss;
    __syncthreads();
    float total = 0.f;
#pragma unroll
    for (int i = 0; i < 8; i++) total += red[i];

    const float scale = rsqrtf(total * (1.0f / DIMN) + EPS_F);

    const float4 g0 = *(const float4*)&J.g[t * 4];
    const float4 g1 = *(const float4*)&J.g[1024 + t * 4];
    v0.x *= scale * g0.x; v0.y *= scale * g0.y; v0.z *= scale * g0.z; v0.w *= scale * g0.w;
    v1.x *= scale * g1.x; v1.y *= scale * g1.y; v1.z *= scale * g1.z; v1.w *= scale * g1.w;

    uint32_t h0, l0, h1, l1;
    split2(make_float2(v0.x, v0.y), h0, l0);
    split2(make_float2(v0.z, v0.w), h1, l1);
    *(uint2*)(J.H + (long)row * DIMN + t * 4) = make_uint2(h0, h1);
    *(uint2*)(J.L + (long)row * DIMN + t * 4) = make_uint2(l0, l1);
    split2(make_float2(v1.x, v1.y), h0, l0);
    split2(make_float2(v1.z, v1.w), h1, l1);
    *(uint2*)(J.H + (long)row * DIMN + 1024 + t * 4) = make_uint2(h0, h1);
    *(uint2*)(J.L + (long)row * DIMN + 1024 + t * 4) = make_uint2(l0, l1);
}

// ---------------- flash attention (img + txt), HMMA 3-term ------------------
// q-tile 128, 8 warps (16 q-rows each, full 64-key chunk width).
// Q + online stats + O register-resident; K/V double-buffered cp.async.
// chunks: 5 img (valid 257) + ceil(lens[b]/64) txt chunks (lens-trimmed).
#define KVB 34816                    /* one K or V buffer: hi 64x272 + lo */
#define OST_OFF (4 * KVB)            /* 139264 */
#define ATT_SMEM (OST_OFF + 128 * 128 * 4)   /* 204800 */

__global__ __launch_bounds__(256, 1)
void attn_kernel(const int* __restrict__ lens)
{
    extern __shared__ char smraw[];
    const uint32_t smb = smem_u32(smraw);
    float* Ost = (float*)(smraw + OST_OFF);

    const int qt = blockIdx.x, h = blockIdx.y, b = blockIdx.z;
    const int tid = threadIdx.x;
    const int wq = tid >> 5;
    const int lane = tid & 31;
    const int q0 = qt * 128;

    const int vtxt = min(lens[b], TXT_T);
    const int nch = 5 + ((vtxt + 63) >> 6);       // 9..13 chunks
    const size_t ibase = (size_t)b * IMG_T * DIMN + h * HDIM;
    const size_t tbase = (size_t)b * TXT_T * DIMN + h * HDIM;

    // ---- stage Q hi/lo into smem (KB area), then ldmatrix into regs ----
    for (int f = tid; f < 2048; f += 256) {
        const int r = f >> 4, c = f & 15;
        const size_t off = ((size_t)(b * LQ + q0 + r)) * DIMN + h * HDIM + c * 8;
        cp16(smb + r * 272 + c * 16,         g_Qh + off);
        cp16(smb + KVB + r * 272 + c * 16,   g_Ql + off);
    }
    CP_COMMIT();
    CP_WAIT(0);
    __syncthreads();

    uint32_t qh[8][4], ql[8][4];
    {
        const uint32_t aQ = smb + (uint32_t)(wq * 16 + (lane & 15)) * 272
                          + ((lane >> 4) * 16);
#pragma unroll
        for (int s8 = 0; s8 < 8; s8++) {
            ldsm4(qh[s8], aQ + s8 * 32);
            ldsm4(ql[s8], aQ + s8 * 32 + KVB);
        }
    }
    __syncthreads();

    // ---- chunk loaders ----
    auto loadK = [&](int ci) {
        if (ci < nch) {
            const __nv_bfloat16 *kh, *kl; int kbase, Lk; size_t base;
            if (ci < 5) { kh = g_Kih; kl = g_Kil; kbase = ci * 64; Lk = IMG_T; base = ibase; }
            else        { kh = g_Kth; kl = g_Ktl; kbase = (ci - 5) * 64; Lk = TXT_T; base = tbase; }
            const uint32_t dst = smb + (ci & 1) * KVB;
            for (int f = tid; f < 1024; f += 256) {
                const int r = f >> 4, cc = f & 15;
                const int kr = kbase + r;
                const int sz = (kr < Lk) ? 16 : 0;
                const int krc = (kr < Lk) ? kr : 0;
                const size_t off = base + (size_t)krc * DIMN + cc * 8;
                cp16z(dst + r * 272 + cc * 16,          kh + off, sz);
                cp16z(dst + 17408 + r * 272 + cc * 16,  kl + off, sz);
            }
        }
        CP_COMMIT();
    };
    auto loadV = [&](int ci) {
        if (ci < nch) {
            const __nv_bfloat16 *vh, *vl; int kbase, Lk; size_t base;
            if (ci < 5) { vh = g_Vih; vl = g_Vil; kbase = ci * 64; Lk = IMG_T; base = ibase; }
            else        { vh = g_Vth; vl = g_Vtl; kbase = (ci - 5) * 64; Lk = TXT_T; base = tbase; }
            const uint32_t dst = smb + 2 * KVB + (ci & 1) * KVB;
            for (int f = tid; f < 1024; f += 256) {
                const int r = f >> 4, cc = f & 15;
                const int kr = kbase + r;
                const int sz = (kr < Lk) ? 16 : 0;
                const int krc = (kr < Lk) ? kr : 0;
                const size_t off = base + (size_t)krc * DIMN + cc * 8;
                cp16z(dst + r * 272 + cc * 16,          vh + off, sz);
                cp16z(dst + 17408 + r * 272 + cc * 16,  vl + off, sz);
            }
        }
        CP_COMMIT();
    };

    float o[16][4];
#pragma unroll
    for (int i = 0; i < 16; i++)
#pragma unroll
        for (int j = 0; j < 4; j++) o[i][j] = 0.f;
    float m0 = -1e30f, m1 = -1e30f, l0 = 0.f, l1 = 0.f;

    const uint32_t kbK = (uint32_t)((lane & 7) + ((lane >> 4) << 3)) * 272
                       + (((lane >> 3) & 1) * 16);
    const uint32_t vbV = (uint32_t)(lane & 15) * 272 + ((lane >> 4) * 16);
    const int qg = lane >> 2;             // row within 16
    const int qc = 2 * (lane & 3);        // col pair base

    // pipeline prologue: K0, V0, K1
    loadK(0); loadV(0); loadK(1);

    for (int ci = 0; ci < nch; ci++) {
        const int buf = ci & 1;
        const int kbase = (ci < 5) ? ci * 64 : (ci - 5) * 64;
        const int valid = (ci < 5) ? IMG_T : vtxt;

        CP_WAIT(2);               // K(ci) ready
        __syncthreads();
        loadV(ci + 1);            // prefetch (VB[buf^1] free)

        // ---- QK scores (3-term) ----
        float s[8][4];
#pragma unroll
        for (int i = 0; i < 8; i++)
#pragma unroll
            for (int j = 0; j < 4; j++) s[i][j] = 0.f;

        const uint32_t KH = smb + buf * KVB;
#pragma unroll
        for (int s8 = 0; s8 < 8; s8++) {
#pragma unroll
            for (int t = 0; t < 4; t++) {
                uint32_t kh_[4], kl_[4];
                ldsm4(kh_, KH + kbK + t * 16 * 272 + s8 * 32);
                ldsm4(kl_, KH + kbK + t * 16 * 272 + s8 * 32 + 17408);
                mma16816(s[2 * t],     qh[s8], kh_[0], kh_[1]);
                mma16816(s[2 * t],     qh[s8], kl_[0], kl_[1]);
                mma16816(s[2 * t],     ql[s8], kh_[0], kh_[1]);
                mma16816(s[2 * t + 1], qh[s8], kh_[2], kh_[3]);
                mma16816(s[2 * t + 1], qh[s8], kl_[2], kl_[3]);
                mma16816(s[2 * t + 1], ql[s8], kh_[2], kh_[3]);
            }
        }

        // ---- online softmax (register-resident, quad reduce) ----
        float cm0 = -1e30f, cm1 = -1e30f;
#pragma unroll
        for (int nt = 0; nt < 8; nt++) {
            const int c0 = kbase + nt * 8 + qc;
#pragma unroll
            for (int j = 0; j < 2; j++) {
                const bool ok = (c0 + j) < valid;
                float t0 = ok ? s[nt][j] * ATT_SCALE : -1e30f;
                float t1 = ok ? s[nt][j + 2] * ATT_SCALE : -1e30f;
                s[nt][j] = t0; s[nt][j + 2] = t1;
                cm0 = fmaxf(cm0, t0); cm1 = fmaxf(cm1, t1);
            }
        }
        cm0 = fmaxf(cm0, __shfl_xor_sync(0xffffffffu, cm0, 1));
        cm0 = fmaxf(cm0, __shfl_xor_sync(0xffffffffu, cm0, 2));
        cm1 = fmaxf(cm1, __shfl_xor_sync(0xffffffffu, cm1, 1));
        cm1 = fmaxf(cm1, __shfl_xor_sync(0xffffffffu, cm1, 2));

        const float mn0 = fmaxf(m0, cm0), mn1 = fmaxf(m1, cm1);
        const float sc0 = __expf(m0 - mn0), sc1 = __expf(m1 - mn1);
        m0 = mn0; m1 = mn1;

        float sum0 = 0.f, sum1 = 0.f;
#pragma unroll
        for (int nt = 0; nt < 8; nt++) {
#pragma unroll
            for (int j = 0; j < 2; j++) {
                float p0 = __expf(s[nt][j] - m0);
                float p1 = __expf(s[nt][j + 2] - m1);
                s[nt][j] = p0; s[nt][j + 2] = p1;
                sum0 += p0; sum1 += p1;
            }
        }
        sum0 += __shfl_xor_sync(0xffffffffu, sum0, 1);
        sum0 += __shfl_xor_sync(0xffffffffu, sum0, 2);
        sum1 += __shfl_xor_sync(0xffffffffu, sum1, 1);
        sum1 += __shfl_xor_sync(0xffffffffu, sum1, 2);
        l0 = l0 * sc0 + sum0;
        l1 = l1 * sc1 + sum1;
#pragma unroll
        for (int nt = 0; nt < 16; nt++) {
            o[nt][0] *= sc0; o[nt][1] *= sc0;
            o[nt][2] *= sc1; o[nt][3] *= sc1;
        }

        CP_WAIT(2);               // V(ci) ready
        __syncthreads();
        loadK(ci + 2);            // prefetch (KB[buf] done)

        // ---- P @ V (3-term; P C-frags reused as A-frags) ----
        const uint32_t VH = smb + 2 * KVB + buf * KVB;
#pragma unroll
        for (int kk = 0; kk < 4; kk++) {
            uint32_t pah[4], pal[4];
            split2(make_float2(s[2 * kk][0],     s[2 * kk][1]),     pah[0], pal[0]);
            split2(make_float2(s[2 * kk][2],     s[2 * kk][3]),     pah[1], pal[1]);
            split2(make_float2(s[2 * kk + 1][0], s[2 * kk + 1][1]), pah[2], pal[2]);
            split2(make_float2(s[2 * kk + 1][2], s[2 * kk + 1][3]), pah[3], pal[3]);
            const uint32_t va = VH + vbV + kk * 16 * 272;
#pragma unroll
            for (int t = 0; t < 8; t++) {
                uint32_t vh_[4], vl_[4];
                ldsm4t(vh_, va + t * 32);
                ldsm4t(vl_, va + t * 32 + 17408);
                mma16816(o[2 * t],     pah, vh_[0], vh_[1]);
                mma16816(o[2 * t],     pah, vl_[0], vl_[1]);
                mma16816(o[2 * t],     pal, vh_[0], vh_[1]);
                mma16816(o[2 * t + 1], pah, vh_[2], vh_[3]);
                mma16816(o[2 * t + 1], pah, vl_[2], vl_[3]);
                mma16816(o[2 * t + 1], pal, vh_[2], vh_[3]);
            }
        }

        // ---- end of img phase: stash normalized output, reset stats ----
        if (ci == 4) {
            const float i0 = 1.f / l0, i1 = 1.f / l1;
            const int r0 = wq * 16 + qg;
#pragma unroll
            for (int nt = 0; nt < 16; nt++) {
                const int col = nt * 8 + qc;
                *(float2*)&Ost[r0 * 128 + col] =
                    make_float2(o[nt][0] * i0, o[nt][1] * i0);
                *(float2*)&Ost[(r0 + 8) * 128 + col] =
                    make_float2(o[nt][2] * i1, o[nt][3] * i1);
                o[nt][0] = o[nt][1] = o[nt][2] = o[nt][3] = 0.f;
            }
            m0 = m1 = -1e30f; l0 = l1 = 0.f;
        }
    }

    // ---- epilogue: out = img_stash + txt/l, write bf16 hi/lo ----
    const float i0 = 1.f / l0, i1 = 1.f / l1;
    const int r0 = wq * 16 + qg;
#pragma unroll
    for (int nt = 0; nt < 16; nt++) {
        const int col = nt * 8 + qc;
        const float2 e0 = *(const float2*)&Ost[r0 * 128 + col];
        const float2 e1 = *(const float2*)&Ost[(r0 + 8) * 128 + col];
        const int gcol = h * HDIM + col;
        const size_t a0 = (size_t)(b * LQ + q0 + r0) * DIMN + gcol;
        const size_t a1 = (size_t)(b * LQ + q0 + r0 + 8) * DIMN + gcol;
        uint32_t hh, ll;
        split2(make_float2(e0.x + o[nt][0] * i0, e0.y + o[nt][1] * i0), hh, ll);
        *(uint32_t*)&g_ah[a0] = hh;
        *(uint32_t*)&g_al[a0] = ll;
        split2(make_float2(e1.x + o[nt][2] * i1, e1.y + o[nt][3] * i1), hh, ll);
        *(uint32_t*)&g_ah[a1] = hh;
        *(uint32_t*)&g_al[a1] = ll;
    }
}

// ---------------------------- launch ---------------------------------------
extern "C" void kernel_launch(void* const* d_in, const int* in_sizes, int n_in,
                              void* d_out, int out_size)
{
    const float* x        = (const float*)d_in[0];
    const float* context  = (const float*)d_in[1];
    const int*   lens     = (const int*)  d_in[2];
    const float* w_q      = (const float*)d_in[3];
    const float* b_q      = (const float*)d_in[4];
    const float* w_k      = (const float*)d_in[5];
    const float* b_k      = (const float*)d_in[6];
    const float* w_v      = (const float*)d_in[7];
    const float* b_v      = (const float*)d_in[8];
    const float* w_k_img  = (const float*)d_in[9];
    const float* b_k_img  = (const float*)d_in[10];
    const float* w_v_img  = (const float*)d_in[11];
    const float* b_v_img  = (const float*)d_in[12];
    const float* w_o      = (const float*)d_in[13];
    const float* b_o      = (const float*)d_in[14];
    const float* g_q      = (const float*)d_in[15];
    const float* g_k      = (const float*)d_in[16];
    const float* g_k_img  = (const float*)d_in[17];
    float* out = (float*)d_out;

    float *Qb, *Ktb, *Kib;
    cudaGetSymbolAddress((void**)&Qb,  g_Q);
    cudaGetSymbolAddress((void**)&Ktb, g_Ktxt);
    cudaGetSymbolAddress((void**)&Kib, g_Kimg);

    __nv_bfloat16 *xh, *xl, *ah, *al, *cth, *ctl, *cih, *cil;
    __nv_bfloat16 *wqh, *wql, *wkh, *wkl, *wvh, *wvl, *wkih, *wkil, *wvih, *wvil, *woh, *wol;
    __nv_bfloat16 *Qhp, *Qlp, *Kthp, *Ktlp, *Vthp, *Vtlp, *Kihp, *Kilp, *Vihp, *Vilp;
    cudaGetSymbolAddress((void**)&xh,  g_xh);   cudaGetSymbolAddress((void**)&xl,  g_xl);
    cudaGetSymbolAddress((void**)&ah,  g_ah);   cudaGetSymbolAddress((void**)&al,  g_al);
    cudaGetSymbolAddress((void**)&cth, g_cth);  cudaGetSymbolAddress((void**)&ctl, g_ctl);
    cudaGetSymbolAddress((void**)&cih, g_cih);  cudaGetSymbolAddress((void**)&cil, g_cil);
    cudaGetSymbolAddress((void**)&wqh, g_wqh);  cudaGetSymbolAddress((void**)&wql, g_wql);
    cudaGetSymbolAddress((void**)&wkh, g_wkh);  cudaGetSymbolAddress((void**)&wkl, g_wkl);
    cudaGetSymbolAddress((void**)&wvh, g_wvh);  cudaGetSymbolAddress((void**)&wvl, g_wvl);
    cudaGetSymbolAddress((void**)&wkih, g_wkih); cudaGetSymbolAddress((void**)&wkil, g_wkil);
    cudaGetSymbolAddress((void**)&wvih, g_wvih); cudaGetSymbolAddress((void**)&wvil, g_wvil);
    cudaGetSymbolAddress((void**)&woh, g_woh);  cudaGetSymbolAddress((void**)&wol, g_wol);
    cudaGetSymbolAddress((void**)&Qhp, g_Qh);   cudaGetSymbolAddress((void**)&Qlp, g_Ql);
    cudaGetSymbolAddress((void**)&Kthp, g_Kth); cudaGetSymbolAddress((void**)&Ktlp, g_Ktl);
    cudaGetSymbolAddress((void**)&Vthp, g_Vth); cudaGetSymbolAddress((void**)&Vtlp, g_Vtl);
    cudaGetSymbolAddress((void**)&Kihp, g_Kih); cudaGetSymbolAddress((void**)&Kilp, g_Kil);
    cudaGetSymbolAddress((void**)&Vihp, g_Vih); cudaGetSymbolAddress((void**)&Vilp, g_Vil);

    cudaFuncSetAttribute(gemm_batch, cudaFuncAttributeMaxDynamicSharedMemorySize, GEMM_SMEM);
    cudaFuncSetAttribute(attn_kernel, cudaFuncAttributeMaxDynamicSharedMemorySize, ATT_SMEM);

    // one batched conversion launch (9 jobs)
    // blocks per job = rows * 2  (1024 elems per block)
    CParams CP;
    int blk = 0;
    auto addc = [&](const float* s, __nv_bfloat16* H, __nv_bfloat16* L,
                    int Mvalid, int Mpad, int rows_pb, int bstride, int roff, int idx) {
        CP.j[idx] = { s, H, L, Mvalid, rows_pb, bstride, roff, blk };
        blk += Mpad * 2;
    };
    addc(x,       xh,   xl,   BATCH * LQ,    BATCH * LQ,    BATCH * LQ, 0, 0, 0);
    addc(w_q,     wqh,  wql,  DIMN, DIMN, DIMN, 0, 0, 1);
    addc(w_k,     wkh,  wkl,  DIMN, DIMN, DIMN, 0, 0, 2);
    addc(w_v,     wvh,  wvl,  DIMN, DIMN, DIMN, 0, 0, 3);
    addc(w_k_img, wkih, wkil, DIMN, DIMN, DIMN, 0, 0, 4);
    addc(w_v_img, wvih, wvil, DIMN, DIMN, DIMN, 0, 0, 5);
    addc(w_o,     woh,  wol,  DIMN, DIMN, DIMN, 0, 0, 6);
    addc(context, cth,  ctl,  BATCH * TXT_T, BATCH * TXT_T, TXT_T, LCTX, IMG_T, 7);
    addc(context, cih,  cil,  BATCH * IMG_T, MPAD_IMG,      IMG_T, LCTX, 0, 8);
    cvt_batch<<<blk, 256>>>(CP);

    // batched projection GEMMs: Q, K_txt, V_txt, K_img, V_img (one launch)
    GParams P;
    P.j[0] = { xh,  xl,  wqh,  wql,  b_q,     Qb,  nullptr, nullptr, BATCH * LQ,    0    };
    P.j[1] = { cth, ctl, wkh,  wkl,  b_k,     Ktb, nullptr, nullptr, BATCH * TXT_T, 1024 };
    P.j[2] = { cth, ctl, wvh,  wvl,  b_v,     nullptr, Vthp, Vtlp,   BATCH * TXT_T, 1152 };
    P.j[3] = { cih, cil, wkih, wkil, b_k_img, Kib, nullptr, nullptr, BATCH * IMG_T, 1280 };
    P.j[4] = { cih, cil, wvih, wvil, b_v_img, nullptr, Vihp, Vilp,   BATCH * IMG_T, 1360 };
    gemm_batch<<<1440, 256, GEMM_SMEM>>>(P);

    // one batched rmsnorm+split launch (Q, K_txt, K_img)
    RParams RP;
    RP.j[0] = { Qb,  g_q,     Qhp,  Qlp,  0 };
    RP.j[1] = { Ktb, g_k,     Kthp, Ktlp, BATCH * LQ };
    RP.j[2] = { Kib, g_k_img, Kihp, Kilp, BATCH * LQ + BATCH * TXT_T };
    rmsnorm_batch<<<BATCH * LQ + BATCH * TXT_T + BATCH * IMG_T, 256>>>(RP);

    // flash attention (img + txt, lens-trimmed) -> g_ah/g_al (bf16 hi/lo)
    attn_kernel<<<dim3(LQ / 128, NHEADS, BATCH), 256, ATT_SMEM>>>(lens);

    // out = attn @ w_o^T + b_o (single-job batched kernel)
    GParams PO;
    PO.j[0] = { ah, al, woh, wol, b_o, out, nullptr, nullptr, BATCH * LQ, 0 };
    PO.j[1] = PO.j[2] = PO.j[3] = PO.j[4] = PO.j[0];
    PO.j[1].cta0 = PO.j[2].cta0 = PO.j[3].cta0 = PO.j[4].cta0 = 1 << 30;
    gemm_batch<<<1024, 256, GEMM_SMEM>>>(PO);
}

// round 14
// speedup vs baseline: 1.0004x; 1.0004x over previous
#include <cuda_runtime.h>
#include <cuda_bf16.h>
#include <math.h>
#include <stdint.h>

#define DIMN 2048
#define NHEADS 16
#define HDIM 128
#define BATCH 2
#define LQ 4096
#define LCTX 769
#define IMG_T 257
#define TXT_T 512
#define EPS_F 1e-6f
#define ATT_SCALE 0.08838834764831845f  /* 1/sqrt(128) */

// ---------------- scratch (device globals; no allocs allowed) --------------
__device__ float g_Q   [BATCH * LQ    * DIMN];
__device__ float g_Ktxt[BATCH * TXT_T * DIMN];
__device__ float g_Kimg[BATCH * IMG_T * DIMN];

// bf16 hi/lo split buffers
#define MPAD_IMG 640
__device__ __nv_bfloat16 g_xh [BATCH * LQ * DIMN];
__device__ __nv_bfloat16 g_xl [BATCH * LQ * DIMN];
__device__ __nv_bfloat16 g_ah [BATCH * LQ * DIMN];
__device__ __nv_bfloat16 g_al [BATCH * LQ * DIMN];
__device__ __nv_bfloat16 g_cth[BATCH * TXT_T * DIMN];
__device__ __nv_bfloat16 g_ctl[BATCH * TXT_T * DIMN];
__device__ __nv_bfloat16 g_cih[MPAD_IMG * DIMN];
__device__ __nv_bfloat16 g_cil[MPAD_IMG * DIMN];
__device__ __nv_bfloat16 g_wqh [DIMN * DIMN], g_wql [DIMN * DIMN];
__device__ __nv_bfloat16 g_wkh [DIMN * DIMN], g_wkl [DIMN * DIMN];
__device__ __nv_bfloat16 g_wvh [DIMN * DIMN], g_wvl [DIMN * DIMN];
__device__ __nv_bfloat16 g_wkih[DIMN * DIMN], g_wkil[DIMN * DIMN];
__device__ __nv_bfloat16 g_wvih[DIMN * DIMN], g_wvil[DIMN * DIMN];
__device__ __nv_bfloat16 g_woh [DIMN * DIMN], g_wol [DIMN * DIMN];

// attention-side hi/lo operands
__device__ __nv_bfloat16 g_Qh [BATCH * LQ * DIMN],    g_Ql [BATCH * LQ * DIMN];
__device__ __nv_bfloat16 g_Kth[BATCH * TXT_T * DIMN], g_Ktl[BATCH * TXT_T * DIMN];
__device__ __nv_bfloat16 g_Vth[BATCH * TXT_T * DIMN], g_Vtl[BATCH * TXT_T * DIMN];
__device__ __nv_bfloat16 g_Kih[BATCH * IMG_T * DIMN], g_Kil[BATCH * IMG_T * DIMN];
__device__ __nv_bfloat16 g_Vih[MPAD_IMG * DIMN],      g_Vil[MPAD_IMG * DIMN];

// ---------------------------- helpers ---------------------------------------
__device__ __forceinline__ uint32_t smem_u32(const void* p) {
    uint32_t a;
    asm("{ .reg .u64 t; cvta.to.shared.u64 t, %1; cvt.u32.u64 %0, t; }"
        : "=r"(a) : "l"(p));
    return a;
}

__device__ __forceinline__ void mma16816(float* d, const uint32_t* a,
                                         const uint32_t b0, const uint32_t b1) {
    asm volatile(
        "mma.sync.aligned.m16n8k16.row.col.f32.bf16.bf16.f32 "
        "{%0,%1,%2,%3}, {%4,%5,%6,%7}, {%8,%9}, {%0,%1,%2,%3};"
        : "+f"(d[0]), "+f"(d[1]), "+f"(d[2]), "+f"(d[3])
        : "r"(a[0]), "r"(a[1]), "r"(a[2]), "r"(a[3]), "r"(b0), "r"(b1));
}

__device__ __forceinline__ void ldsm4(uint32_t* r, uint32_t a) {
    asm volatile("ldmatrix.sync.aligned.m8n8.x4.shared.b16 {%0,%1,%2,%3}, [%4];"
                 : "=r"(r[0]), "=r"(r[1]), "=r"(r[2]), "=r"(r[3]) : "r"(a));
}
__device__ __forceinline__ void ldsm4t(uint32_t* r, uint32_t a) {
    asm volatile("ldmatrix.sync.aligned.m8n8.x4.trans.shared.b16 {%0,%1,%2,%3}, [%4];"
                 : "=r"(r[0]), "=r"(r[1]), "=r"(r[2]), "=r"(r[3]) : "r"(a));
}
__device__ __forceinline__ void cp16(uint32_t d, const void* s) {
    asm volatile("cp.async.cg.shared.global [%0], [%1], 16;"
                 :: "r"(d), "l"(s) : "memory");
}
__device__ __forceinline__ void cp16z(uint32_t d, const void* s, int sz) {
    asm volatile("cp.async.cg.shared.global [%0], [%1], 16, %2;"
                 :: "r"(d), "l"(s), "r"(sz) : "memory");
}
#define CP_COMMIT() asm volatile("cp.async.commit_group;" ::: "memory")
#define CP_WAIT(n)  asm volatile("cp.async.wait_group %0;" :: "n"(n) : "memory")

// f32x2 -> bf16x2 hi + lo residual
__device__ __forceinline__ void split2(float2 f, uint32_t& h, uint32_t& l) {
    __nv_bfloat162 hb = __float22bfloat162_rn(f);
    float2 hf = __bfloat1622float2(hb);
    __nv_bfloat162 lb = __float22bfloat162_rn(make_float2(f.x - hf.x, f.y - hf.y));
    h = *(uint32_t*)&hb;
    l = *(uint32_t*)&lb;
}

// -------------- batched fp32 -> bf16 hi/lo split (9 jobs, one launch) ------
struct CJob {
    const float* src;
    __nv_bfloat16 *hi, *lo;
    int Mvalid, rows_pb, bstride, roff, blk0;
};
struct CParams { CJob j[9]; };

__global__ __launch_bounds__(256)
void cvt_batch(CParams P)
{
    const int bid = blockIdx.x;
    int ji = 0;
#pragma unroll
    for (int k = 1; k < 9; k++) if (bid >= P.j[k].blk0) ji = k;
    const CJob& J = P.j[ji];

    const long e = (long)(bid - J.blk0) * 1024 + threadIdx.x * 4;
    const int m = (int)(e >> 11);
    const int col = (int)(e & 2047);

    float4 v = make_float4(0.f, 0.f, 0.f, 0.f);
    if (m < J.Mvalid) {
        const int bb = m / J.rows_pb;
        const long srow = (long)bb * J.bstride + J.roff + (m - bb * J.rows_pb);
        v = *(const float4*)(J.src + srow * DIMN + col);
    }
    uint32_t h0, l0, h1, l1;
    split2(make_float2(v.x, v.y), h0, l0);
    split2(make_float2(v.z, v.w), h1, l1);
    *(uint2*)(J.hi + e) = make_uint2(h0, h1);
    *(uint2*)(J.lo + e) = make_uint2(l0, l1);
}

// ------------- batched HMMA GEMM: C = (Ah+Al)(Bh+Bl)^T + bias (3 terms) ----
#define GT_KC 32
#define NCHUNK (DIMN / GT_KC)        /* 64 */
#define TILE_B   10240               /* 128 x 80 bytes */
#define BUF_B    (4 * TILE_B)
#define GEMM_SMEM (2 * BUF_B)

struct GJob {
    const __nv_bfloat16 *Ah, *Al, *Bh, *Bl;
    const float *bias;
    float *C;                      // fp32 out (may be null)
    __nv_bfloat16 *Ch, *Cl;        // hi/lo out (may be null)
    int Mvalid;
    int cta0;
};
struct GParams { GJob j[5]; };

__global__ __launch_bounds__(256, 2)
void gemm_batch(GParams P)
{
    extern __shared__ __nv_bfloat16 sm[];

    const int bid = blockIdx.x;
    int ji = 0;
#pragma unroll
    for (int k = 1; k < 5; k++) if (bid >= P.j[k].cta0) ji = k;
    const GJob& J = P.j[ji];
    const int local = bid - J.cta0;
    const int n0 = (local & 15) * 128;
    const int m0 = (local >> 4) * 128;

    const int tid = threadIdx.x;
    const int wid = tid >> 5;
    const int lane = tid & 31;
    const int wm = wid & 3;
    const int wn = wid >> 2;

    const __nv_bfloat16* srcs[4] = {
        J.Ah + (size_t)m0 * DIMN, J.Al + (size_t)m0 * DIMN,
        J.Bh + (size_t)n0 * DIMN, J.Bl + (size_t)n0 * DIMN };

    const uint32_t smb = smem_u32(sm);

    auto load_chunk = [&](int c, int b) {
        const int k0 = c * GT_KC;
#pragma unroll
        for (int j = 0; j < 8; j++) {
            const int f = j * 256 + tid;
            const int tile = f >> 9;
            const int w = f & 511;
            const int r = w >> 2;
            const int cc = w & 3;
            const __nv_bfloat16* sp = srcs[tile] + (size_t)r * DIMN + k0 + cc * 8;
            cp16(smb + b * BUF_B + tile * TILE_B + r * 80 + cc * 16, sp);
        }
        CP_COMMIT();
    };

    float acc[2][8][4];
#pragma unroll
    for (int i = 0; i < 2; i++)
#pragma unroll
        for (int j = 0; j < 8; j++)
#pragma unroll
            for (int q = 0; q < 4; q++) acc[i][j][q] = 0.f;

    const uint32_t aOff = (uint32_t)(wm * 32 + (lane & 15)) * 80 + ((lane >> 4) * 16);
    const uint32_t bOff = (uint32_t)(wn * 64 + (lane & 7) + ((lane >> 4) << 3)) * 80
                        + (((lane >> 3) & 1) * 16) + 2 * TILE_B;

    load_chunk(0, 0);
    load_chunk(1, 1);

    for (int c = 0; c < NCHUNK; c++) {
        const int b = c & 1;
        if (c == NCHUNK - 1) CP_WAIT(0);
        else                 CP_WAIT(1);
        __syncthreads();

        const uint32_t buf = smb + b * BUF_B;

#pragma unroll
        for (int s = 0; s < 2; s++) {
            uint32_t ah_[2][4], al_[2][4];
#pragma unroll
            for (int mt = 0; mt < 2; mt++) {
                ldsm4(ah_[mt], buf + aOff + mt * 16 * 80 + s * 32);
                ldsm4(al_[mt], buf + aOff + mt * 16 * 80 + s * 32 + TILE_B);
            }
#pragma unroll
            for (int t = 0; t < 4; t++) {
                uint32_t bh_[4], bl_[4];
                ldsm4(bh_, buf + bOff + t * 16 * 80 + s * 32);
                ldsm4(bl_, buf + bOff + t * 16 * 80 + s * 32 + TILE_B);
#pragma unroll
                for (int mt = 0; mt < 2; mt++) {
                    mma16816(acc[mt][2 * t],     ah_[mt], bh_[0], bh_[1]);
                    mma16816(acc[mt][2 * t],     ah_[mt], bl_[0], bl_[1]);
                    mma16816(acc[mt][2 * t],     al_[mt], bh_[0], bh_[1]);
                    mma16816(acc[mt][2 * t + 1], ah_[mt], bh_[2], bh_[3]);
                    mma16816(acc[mt][2 * t + 1], ah_[mt], bl_[2], bl_[3]);
                    mma16816(acc[mt][2 * t + 1], al_[mt], bh_[2], bh_[3]);
                }
            }
        }
        __syncthreads();
        if (c + 2 < NCHUNK) load_chunk(c + 2, b);
    }

    const int lr = lane >> 2;
    const int lc = (lane & 3) * 2;
#pragma unroll
    for (int mt = 0; mt < 2; mt++) {
#pragma unroll
        for (int nt = 0; nt < 8; nt++) {
            const int n = n0 + wn * 64 + nt * 8 + lc;
            const float2 bv = *(const float2*)&J.bias[n];
            const int mA = m0 + wm * 32 + mt * 16 + lr;
            float2 o0 = make_float2(acc[mt][nt][0] + bv.x, acc[mt][nt][1] + bv.y);
            float2 o1 = make_float2(acc[mt][nt][2] + bv.x, acc[mt][nt][3] + bv.y);
            if (J.C) {
                if (mA < J.Mvalid)     *(float2*)(J.C + (size_t)mA * DIMN + n) = o0;
                if (mA + 8 < J.Mvalid) *(float2*)(J.C + (size_t)(mA + 8) * DIMN + n) = o1;
            }
            if (J.Ch) {
                uint32_t hh, ll;
                if (mA < J.Mvalid) {
                    split2(o0, hh, ll);
                    *(uint32_t*)(J.Ch + (size_t)mA * DIMN + n) = hh;
                    *(uint32_t*)(J.Cl + (size_t)mA * DIMN + n) = ll;
                }
                if (mA + 8 < J.Mvalid) {
                    split2(o1, hh, ll);
                    *(uint32_t*)(J.Ch + (size_t)(mA + 8) * DIMN + n) = hh;
                    *(uint32_t*)(J.Cl + (size_t)(mA + 8) * DIMN + n) = ll;
                }
            }
        }
    }
}

// ------------- batched RMS norm -> bf16 hi/lo split (3 jobs) ---------------
struct RJob {
    const float* X;
    const float* g;
    __nv_bfloat16 *H, *L;
    int row0;
};
struct RParams { RJob j[3]; };

__global__ __launch_bounds__(256)
void rmsnorm_batch(RParams P)
{
    const int bid = blockIdx.x;
    int ji = 0;
#pragma unroll
    for (int k = 1; k < 3; k++) if (bid >= P.j[k].row0) ji = k;
    const RJob& J = P.j[ji];
    const int row = bid - J.row0;

    const float* xr = J.X + (long)row * DIMN;
    const int t = threadIdx.x;

    float4 v0 = *(const float4*)&xr[t * 4];
    float4 v1 = *(const float4*)&xr[1024 + t * 4];
    float ss = v0.x * v0.x + v0.y * v0.y + v0.z * v0.z + v0.w * v0.w
             + v1.x * v1.x + v1.y * v1.y + v1.z * v1.z + v1.w * v1.w;

#pragma unroll
    for (int o = 16; o > 0; o >>= 1) ss += __shfl_xor_sync(0xffffffffu, ss, o);

    __shared__ float red[8];
    if ((t & 31) == 0) red[t >> 5] = ss;
    __syncthreads();
    float total = 0.f;
#pragma unroll
    for (int i = 0; i < 8; i++) total += red[i];

    const float scale = rsqrtf(total * (1.0f / DIMN) + EPS_F);

    const float4 g0 = *(const float4*)&J.g[t * 4];
    const float4 g1 = *(const float4*)&J.g[1024 + t * 4];
    v0.x *= scale * g0.x; v0.y *= scale * g0.y; v0.z *= scale * g0.z; v0.w *= scale * g0.w;
    v1.x *= scale * g1.x; v1.y *= scale * g1.y; v1.z *= scale * g1.z; v1.w *= scale * g1.w;

    uint32_t h0, l0, h1, l1;
    split2(make_float2(v0.x, v0.y), h0, l0);
    split2(make_float2(v0.z, v0.w), h1, l1);
    *(uint2*)(J.H + (long)row * DIMN + t * 4) = make_uint2(h0, h1);
    *(uint2*)(J.L + (long)row * DIMN + t * 4) = make_uint2(l0, l1);
    split2(make_float2(v1.x, v1.y), h0, l0);
    split2(make_float2(v1.z, v1.w), h1, l1);
    *(uint2*)(J.H + (long)row * DIMN + 1024 + t * 4) = make_uint2(h0, h1);
    *(uint2*)(J.L + (long)row * DIMN + 1024 + t * 4) = make_uint2(l0, l1);
}

// ---------------- flash attention (img + txt), HMMA 3-term ------------------
// q-tile 128, 8 warps (16 q-rows each, full 64-key chunk width).
// Q + online stats + O register-resident; K/V double-buffered cp.async.
// chunks: 5 img (valid 257) + ceil(lens[b]/64) txt chunks (lens-trimmed).
#define KVB 34816                    /* one K or V buffer: hi 64x272 + lo */
#define OST_OFF (4 * KVB)            /* 139264 */
#define ATT_SMEM (OST_OFF + 128 * 128 * 4)   /* 204800 */

__global__ __launch_bounds__(256, 1)
void attn_kernel(const int* __restrict__ lens)
{
    extern __shared__ char smraw[];
    const uint32_t smb = smem_u32(smraw);
    float* Ost = (float*)(smraw + OST_OFF);

    const int qt = blockIdx.x, h = blockIdx.y, b = blockIdx.z;
    const int tid = threadIdx.x;
    const int wq = tid >> 5;
    const int lane = tid & 31;
    const int q0 = qt * 128;

    const int vtxt = min(lens[b], TXT_T);
    const int nch = 5 + ((vtxt + 63) >> 6);       // 9..13 chunks
    const size_t ibase = (size_t)b * IMG_T * DIMN + h * HDIM;
    const size_t tbase = (size_t)b * TXT_T * DIMN + h * HDIM;

    // ---- stage Q hi/lo into smem (KB area), then ldmatrix into regs ----
    for (int f = tid; f < 2048; f += 256) {
        const int r = f >> 4, c = f & 15;
        const size_t off = ((size_t)(b * LQ + q0 + r)) * DIMN + h * HDIM + c * 8;
        cp16(smb + r * 272 + c * 16,         g_Qh + off);
        cp16(smb + KVB + r * 272 + c * 16,   g_Ql + off);
    }
    CP_COMMIT();
    CP_WAIT(0);
    __syncthreads();

    uint32_t qh[8][4], ql[8][4];
    {
        const uint32_t aQ = smb + (uint32_t)(wq * 16 + (lane & 15)) * 272
                          + ((lane >> 4) * 16);
#pragma unroll
        for (int s8 = 0; s8 < 8; s8++) {
            ldsm4(qh[s8], aQ + s8 * 32);
            ldsm4(ql[s8], aQ + s8 * 32 + KVB);
        }
    }
    __syncthreads();

    // ---- chunk loaders ----
    auto loadK = [&](int ci) {
        if (ci < nch) {
            const __nv_bfloat16 *kh, *kl; int kbase, Lk; size_t base;
            if (ci < 5) { kh = g_Kih; kl = g_Kil; kbase = ci * 64; Lk = IMG_T; base = ibase; }
            else        { kh = g_Kth; kl = g_Ktl; kbase = (ci - 5) * 64; Lk = TXT_T; base = tbase; }
            const uint32_t dst = smb + (ci & 1) * KVB;
            for (int f = tid; f < 1024; f += 256) {
                const int r = f >> 4, cc = f & 15;
                const int kr = kbase + r;
                const int sz = (kr < Lk) ? 16 : 0;
                const int krc = (kr < Lk) ? kr : 0;
                const size_t off = base + (size_t)krc * DIMN + cc * 8;
                cp16z(dst + r * 272 + cc * 16,          kh + off, sz);
                cp16z(dst + 17408 + r * 272 + cc * 16,  kl + off, sz);
            }
        }
        CP_COMMIT();
    };
    auto loadV = [&](int ci) {
        if (ci < nch) {
            const __nv_bfloat16 *vh, *vl; int kbase, Lk; size_t base;
            if (ci < 5) { vh = g_Vih; vl = g_Vil; kbase = ci * 64; Lk = IMG_T; base = ibase; }
            else        { vh = g_Vth; vl = g_Vtl; kbase = (ci - 5) * 64; Lk = TXT_T; base = tbase; }
            const uint32_t dst = smb + 2 * KVB + (ci & 1) * KVB;
            for (int f = tid; f < 1024; f += 256) {
                const int r = f >> 4, cc = f & 15;
                const int kr = kbase + r;
                const int sz = (kr < Lk) ? 16 : 0;
                const int krc = (kr < Lk) ? kr : 0;
                const size_t off = base + (size_t)krc * DIMN + cc * 8;
                cp16z(dst + r * 272 + cc * 16,          vh + off, sz);
                cp16z(dst + 17408 + r * 272 + cc * 16,  vl + off, sz);
            }
        }
        CP_COMMIT();
    };

    float o[16][4];
#pragma unroll
    for (int i = 0; i < 16; i++)
#pragma unroll
        for (int j = 0; j < 4; j++) o[i][j] = 0.f;
    float m0 = -1e30f, m1 = -1e30f, l0 = 0.f, l1 = 0.f;

    const uint32_t kbK = (uint32_t)((lane & 7) + ((lane >> 4) << 3)) * 272
                       + (((lane >> 3) & 1) * 16);
    const uint32_t vbV = (uint32_t)(lane & 15) * 272 + ((lane >> 4) * 16);
    const int qg = lane >> 2;             // row within 16
    const int qc = 2 * (lane & 3);        // col pair base

    // pipeline prologue: K0, V0, K1
    loadK(0); loadV(0); loadK(1);

    for (int ci = 0; ci < nch; ci++) {
        const int buf = ci & 1;
        const int kbase = (ci < 5) ? ci * 64 : (ci - 5) * 64;
        const int valid = (ci < 5) ? IMG_T : vtxt;

        CP_WAIT(2);               // K(ci) ready
        __syncthreads();
        loadV(ci + 1);            // prefetch (VB[buf^1] free)

        // ---- QK scores (3-term) ----
        float s[8][4];
#pragma unroll
        for (int i = 0; i < 8; i++)
#pragma unroll
            for (int j = 0; j < 4; j++) s[i][j] = 0.f;

        const uint32_t KH = smb + buf * KVB;
#pragma unroll
        for (int s8 = 0; s8 < 8; s8++) {
#pragma unroll
            for (int t = 0; t < 4; t++) {
                uint32_t kh_[4], kl_[4];
                ldsm4(kh_, KH + kbK + t * 16 * 272 + s8 * 32);
                ldsm4(kl_, KH + kbK + t * 16 * 272 + s8 * 32 + 17408);
                mma16816(s[2 * t],     qh[s8], kh_[0], kh_[1]);
                mma16816(s[2 * t],     qh[s8], kl_[0], kl_[1]);
                mma16816(s[2 * t],     ql[s8], kh_[0], kh_[1]);
                mma16816(s[2 * t + 1], qh[s8], kh_[2], kh_[3]);
                mma16816(s[2 * t + 1], qh[s8], kl_[2], kl_[3]);
                mma16816(s[2 * t + 1], ql[s8], kh_[2], kh_[3]);
            }
        }

        // ---- online softmax (register-resident, quad reduce) ----
        float cm0 = -1e30f, cm1 = -1e30f;
#pragma unroll
        for (int nt = 0; nt < 8; nt++) {
            const int c0 = kbase + nt * 8 + qc;
#pragma unroll
            for (int j = 0; j < 2; j++) {
                const bool ok = (c0 + j) < valid;
                float t0 = ok ? s[nt][j] * ATT_SCALE : -1e30f;
                float t1 = ok ? s[nt][j + 2] * ATT_SCALE : -1e30f;
                s[nt][j] = t0; s[nt][j + 2] = t1;
                cm0 = fmaxf(cm0, t0); cm1 = fmaxf(cm1, t1);
            }
        }
        cm0 = fmaxf(cm0, __shfl_xor_sync(0xffffffffu, cm0, 1));
        cm0 = fmaxf(cm0, __shfl_xor_sync(0xffffffffu, cm0, 2));
        cm1 = fmaxf(cm1, __shfl_xor_sync(0xffffffffu, cm1, 1));
        cm1 = fmaxf(cm1, __shfl_xor_sync(0xffffffffu, cm1, 2));

        const float mn0 = fmaxf(m0, cm0), mn1 = fmaxf(m1, cm1);
        const float sc0 = __expf(m0 - mn0), sc1 = __expf(m1 - mn1);
        m0 = mn0; m1 = mn1;

        float sum0 = 0.f, sum1 = 0.f;
#pragma unroll
        for (int nt = 0; nt < 8; nt++) {
#pragma unroll
            for (int j = 0; j < 2; j++) {
                float p0 = __expf(s[nt][j] - m0);
                float p1 = __expf(s[nt][j + 2] - m1);
                s[nt][j] = p0; s[nt][j + 2] = p1;
                sum0 += p0; sum1 += p1;
            }
        }
        sum0 += __shfl_xor_sync(0xffffffffu, sum0, 1);
        sum0 += __shfl_xor_sync(0xffffffffu, sum0, 2);
        sum1 += __shfl_xor_sync(0xffffffffu, sum1, 1);
        sum1 += __shfl_xor_sync(0xffffffffu, sum1, 2);
        l0 = l0 * sc0 + sum0;
        l1 = l1 * sc1 + sum1;
#pragma unroll
        for (int nt = 0; nt < 16; nt++) {
            o[nt][0] *= sc0; o[nt][1] *= sc0;
            o[nt][2] *= sc1; o[nt][3] *= sc1;
        }

        CP_WAIT(2);               // V(ci) ready
        __syncthreads();
        loadK(ci + 2);            // prefetch (KB[buf] done)

        // ---- P @ V (3-term; P C-frags reused as A-frags) ----
        const uint32_t VH = smb + 2 * KVB + buf * KVB;
#pragma unroll
        for (int kk = 0; kk < 4; kk++) {
            uint32_t pah[4], pal[4];
            split2(make_float2(s[2 * kk][0],     s[2 * kk][1]),     pah[0], pal[0]);
            split2(make_float2(s[2 * kk][2],     s[2 * kk][3]),     pah[1], pal[1]);
            split2(make_float2(s[2 * kk + 1][0], s[2 * kk + 1][1]), pah[2], pal[2]);
            split2(make_float2(s[2 * kk + 1][2], s[2 * kk + 1][3]), pah[3], pal[3]);
            const uint32_t va = VH + vbV + kk * 16 * 272;
#pragma unroll
            for (int t = 0; t < 8; t++) {
                uint32_t vh_[4], vl_[4];
                ldsm4t(vh_, va + t * 32);
                ldsm4t(vl_, va + t * 32 + 17408);
                mma16816(o[2 * t],     pah, vh_[0], vh_[1]);
                mma16816(o[2 * t],     pah, vl_[0], vl_[1]);
                mma16816(o[2 * t],     pal, vh_[0], vh_[1]);
                mma16816(o[2 * t + 1], pah, vh_[2], vh_[3]);
                mma16816(o[2 * t + 1], pah, vl_[2], vl_[3]);
                mma16816(o[2 * t + 1], pal, vh_[2], vh_[3]);
            }
        }

        // ---- end of img phase: stash normalized output, reset stats ----
        if (ci == 4) {
            const float i0 = 1.f / l0, i1 = 1.f / l1;
            const int r0 = wq * 16 + qg;
#pragma unroll
            for (int nt = 0; nt < 16; nt++) {
                const int col = nt * 8 + qc;
                *(float2*)&Ost[r0 * 128 + col] =
                    make_float2(o[nt][0] * i0, o[nt][1] * i0);
                *(float2*)&Ost[(r0 + 8) * 128 + col] =
                    make_float2(o[nt][2] * i1, o[nt][3] * i1);
                o[nt][0] = o[nt][1] = o[nt][2] = o[nt][3] = 0.f;
            }
            m0 = m1 = -1e30f; l0 = l1 = 0.f;
        }
    }

    // ---- epilogue: out = img_stash + txt/l, write bf16 hi/lo ----
    const float i0 = 1.f / l0, i1 = 1.f / l1;
    const int r0 = wq * 16 + qg;
#pragma unroll
    for (int nt = 0; nt < 16; nt++) {
        const int col = nt * 8 + qc;
        const float2 e0 = *(const float2*)&Ost[r0 * 128 + col];
        const float2 e1 = *(const float2*)&Ost[(r0 + 8) * 128 + col];
        const int gcol = h * HDIM + col;
        const size_t a0 = (size_t)(b * LQ + q0 + r0) * DIMN + gcol;
        const size_t a1 = (size_t)(b * LQ + q0 + r0 + 8) * DIMN + gcol;
        uint32_t hh, ll;
        split2(make_float2(e0.x + o[nt][0] * i0, e0.y + o[nt][1] * i0), hh, ll);
        *(uint32_t*)&g_ah[a0] = hh;
        *(uint32_t*)&g_al[a0] = ll;
        split2(make_float2(e1.x + o[nt][2] * i1, e1.y + o[nt][3] * i1), hh, ll);
        *(uint32_t*)&g_ah[a1] = hh;
        *(uint32_t*)&g_al[a1] = ll;
    }
}

// ---------------------------- launch ---------------------------------------
extern "C" void kernel_launch(void* const* d_in, const int* in_sizes, int n_in,
                              void* d_out, int out_size)
{
    const float* x        = (const float*)d_in[0];
    const float* context  = (const float*)d_in[1];
    const int*   lens     = (const int*)  d_in[2];
    const float* w_q      = (const float*)d_in[3];
    const float* b_q      = (const float*)d_in[4];
    const float* w_k      = (const float*)d_in[5];
    const float* b_k      = (const float*)d_in[6];
    const float* w_v      = (const float*)d_in[7];
    const float* b_v      = (const float*)d_in[8];
    const float* w_k_img  = (const float*)d_in[9];
    const float* b_k_img  = (const float*)d_in[10];
    const float* w_v_img  = (const float*)d_in[11];
    const float* b_v_img  = (const float*)d_in[12];
    const float* w_o      = (const float*)d_in[13];
    const float* b_o      = (const float*)d_in[14];
    const float* g_q      = (const float*)d_in[15];
    const float* g_k      = (const float*)d_in[16];
    const float* g_k_img  = (const float*)d_in[17];
    float* out = (float*)d_out;

    float *Qb, *Ktb, *Kib;
    cudaGetSymbolAddress((void**)&Qb,  g_Q);
    cudaGetSymbolAddress((void**)&Ktb, g_Ktxt);
    cudaGetSymbolAddress((void**)&Kib, g_Kimg);

    __nv_bfloat16 *xh, *xl, *ah, *al, *cth, *ctl, *cih, *cil;
    __nv_bfloat16 *wqh, *wql, *wkh, *wkl, *wvh, *wvl, *wkih, *wkil, *wvih, *wvil, *woh, *wol;
    __nv_bfloat16 *Qhp, *Qlp, *Kthp, *Ktlp, *Vthp, *Vtlp, *Kihp, *Kilp, *Vihp, *Vilp;
    cudaGetSymbolAddress((void**)&xh,  g_xh);   cudaGetSymbolAddress((void**)&xl,  g_xl);
    cudaGetSymbolAddress((void**)&ah,  g_ah);   cudaGetSymbolAddress((void**)&al,  g_al);
    cudaGetSymbolAddress((void**)&cth, g_cth);  cudaGetSymbolAddress((void**)&ctl, g_ctl);
    cudaGetSymbolAddress((void**)&cih, g_cih);  cudaGetSymbolAddress((void**)&cil, g_cil);
    cudaGetSymbolAddress((void**)&wqh, g_wqh);  cudaGetSymbolAddress((void**)&wql, g_wql);
    cudaGetSymbolAddress((void**)&wkh, g_wkh);  cudaGetSymbolAddress((void**)&wkl, g_wkl);
    cudaGetSymbolAddress((void**)&wvh, g_wvh);  cudaGetSymbolAddress((void**)&wvl, g_wvl);
    cudaGetSymbolAddress((void**)&wkih, g_wkih); cudaGetSymbolAddress((void**)&wkil, g_wkil);
    cudaGetSymbolAddress((void**)&wvih, g_wvih); cudaGetSymbolAddress((void**)&wvil, g_wvil);
    cudaGetSymbolAddress((void**)&woh, g_woh);  cudaGetSymbolAddress((void**)&wol, g_wol);
    cudaGetSymbolAddress((void**)&Qhp, g_Qh);   cudaGetSymbolAddress((void**)&Qlp, g_Ql);
    cudaGetSymbolAddress((void**)&Kthp, g_Kth); cudaGetSymbolAddress((void**)&Ktlp, g_Ktl);
    cudaGetSymbolAddress((void**)&Vthp, g_Vth); cudaGetSymbolAddress((void**)&Vtlp, g_Vtl);
    cudaGetSymbolAddress((void**)&Kihp, g_Kih); cudaGetSymbolAddress((void**)&Kilp, g_Kil);
    cudaGetSymbolAddress((void**)&Vihp, g_Vih); cudaGetSymbolAddress((void**)&Vilp, g_Vil);

    cudaFuncSetAttribute(gemm_batch, cudaFuncAttributeMaxDynamicSharedMemorySize, GEMM_SMEM);
    cudaFuncSetAttribute(attn_kernel, cudaFuncAttributeMaxDynamicSharedMemorySize, ATT_SMEM);

    // one batched conversion launch (9 jobs)
    // blocks per job = rows * 2  (1024 elems per block)
    CParams CP;
    int blk = 0;
    auto addc = [&](const float* s, __nv_bfloat16* H, __nv_bfloat16* L,
                    int Mvalid, int Mpad, int rows_pb, int bstride, int roff, int idx) {
        CP.j[idx] = { s, H, L, Mvalid, rows_pb, bstride, roff, blk };
        blk += Mpad * 2;
    };
    addc(x,       xh,   xl,   BATCH * LQ,    BATCH * LQ,    BATCH * LQ, 0, 0, 0);
    addc(w_q,     wqh,  wql,  DIMN, DIMN, DIMN, 0, 0, 1);
    addc(w_k,     wkh,  wkl,  DIMN, DIMN, DIMN, 0, 0, 2);
    addc(w_v,     wvh,  wvl,  DIMN, DIMN, DIMN, 0, 0, 3);
    addc(w_k_img, wkih, wkil, DIMN, DIMN, DIMN, 0, 0, 4);
    addc(w_v_img, wvih, wvil, DIMN, DIMN, DIMN, 0, 0, 5);
    addc(w_o,     woh,  wol,  DIMN, DIMN, DIMN, 0, 0, 6);
    addc(context, cth,  ctl,  BATCH * TXT_T, BATCH * TXT_T, TXT_T, LCTX, IMG_T, 7);
    addc(context, cih,  cil,  BATCH * IMG_T, MPAD_IMG,      IMG_T, LCTX, 0, 8);
    cvt_batch<<<blk, 256>>>(CP);

    // batched projection GEMMs: Q, K_txt, V_txt, K_img, V_img (one launch)
    GParams P;
    P.j[0] = { xh,  xl,  wqh,  wql,  b_q,     Qb,  nullptr, nullptr, BATCH * LQ,    0    };
    P.j[1] = { cth, ctl, wkh,  wkl,  b_k,     Ktb, nullptr, nullptr, BATCH * TXT_T, 1024 };
    P.j[2] = { cth, ctl, wvh,  wvl,  b_v,     nullptr, Vthp, Vtlp,   BATCH * TXT_T, 1152 };
    P.j[3] = { cih, cil, wkih, wkil, b_k_img, Kib, nullptr, nullptr, BATCH * IMG_T, 1280 };
    P.j[4] = { cih, cil, wvih, wvil, b_v_img, nullptr, Vihp, Vilp,   BATCH * IMG_T, 1360 };
    gemm_batch<<<1440, 256, GEMM_SMEM>>>(P);

    // one batched rmsnorm+split launch (Q, K_txt, K_img)
    RParams RP;
    RP.j[0] = { Qb,  g_q,     Qhp,  Qlp,  0 };
    RP.j[1] = { Ktb, g_k,     Kthp, Ktlp, BATCH * LQ };
    RP.j[2] = { Kib, g_k_img, Kihp, Kilp, BATCH * LQ + BATCH * TXT_T };
    rmsnorm_batch<<<BATCH * LQ + BATCH * TXT_T + BATCH * IMG_T, 256>>>(RP);

    // flash attention (img + txt, lens-trimmed) -> g_ah/g_al (bf16 hi/lo)
    attn_kernel<<<dim3(LQ / 128, NHEADS, BATCH), 256, ATT_SMEM>>>(lens);

    // out = attn @ w_o^T + b_o (single-job batched kernel)
    GParams PO;
    PO.j[0] = { ah, al, woh, wol, b_o, out, nullptr, nullptr, BATCH * LQ, 0 };
    PO.j[1] = PO.j[2] = PO.j[3] = PO.j[4] = PO.j[0];
    PO.j[1].cta0 = PO.j[2].cta0 = PO.j[3].cta0 = PO.j[4].cta0 = 1 << 30;
    gemm_batch<<<1024, 256, GEMM_SMEM>>>(PO);
}

// round 15
// speedup vs baseline: 1.0014x; 1.0010x over previous
#include <cuda_runtime.h>
#include <cuda_bf16.h>
#include <math.h>
#include <stdint.h>

#define DIMN 2048
#define NHEADS 16
#define HDIM 128
#define BATCH 2
#define LQ 4096
#define LCTX 769
#define IMG_T 257
#define TXT_T 512
#define EPS_F 1e-6f
#define ATT_SCALE 0.08838834764831845f  /* 1/sqrt(128) */

// ---------------- scratch (device globals; no allocs allowed) --------------
__device__ float g_Q   [BATCH * LQ    * DIMN];
__device__ float g_Ktxt[BATCH * TXT_T * DIMN];
__device__ float g_Kimg[BATCH * IMG_T * DIMN];

// bf16 hi/lo split buffers
#define MPAD_IMG 640
__device__ __nv_bfloat16 g_xh [BATCH * LQ * DIMN];
__device__ __nv_bfloat16 g_xl [BATCH * LQ * DIMN];
__device__ __nv_bfloat16 g_ah [BATCH * LQ * DIMN];
__device__ __nv_bfloat16 g_al [BATCH * LQ * DIMN];
__device__ __nv_bfloat16 g_cth[BATCH * TXT_T * DIMN];
__device__ __nv_bfloat16 g_ctl[BATCH * TXT_T * DIMN];
__device__ __nv_bfloat16 g_cih[MPAD_IMG * DIMN];
__device__ __nv_bfloat16 g_cil[MPAD_IMG * DIMN];
__device__ __nv_bfloat16 g_wqh [DIMN * DIMN], g_wql [DIMN * DIMN];
__device__ __nv_bfloat16 g_wkh [DIMN * DIMN], g_wkl [DIMN * DIMN];
__device__ __nv_bfloat16 g_wvh [DIMN * DIMN], g_wvl [DIMN * DIMN];
__device__ __nv_bfloat16 g_wkih[DIMN * DIMN], g_wkil[DIMN * DIMN];
__device__ __nv_bfloat16 g_wvih[DIMN * DIMN], g_wvil[DIMN * DIMN];
__device__ __nv_bfloat16 g_woh [DIMN * DIMN], g_wol [DIMN * DIMN];

// attention-side hi/lo operands
__device__ __nv_bfloat16 g_Qh [BATCH * LQ * DIMN],    g_Ql [BATCH * LQ * DIMN];
__device__ __nv_bfloat16 g_Kth[BATCH * TXT_T * DIMN], g_Ktl[BATCH * TXT_T * DIMN];
__device__ __nv_bfloat16 g_Vth[BATCH * TXT_T * DIMN], g_Vtl[BATCH * TXT_T * DIMN];
__device__ __nv_bfloat16 g_Kih[BATCH * IMG_T * DIMN], g_Kil[BATCH * IMG_T * DIMN];
__device__ __nv_bfloat16 g_Vih[MPAD_IMG * DIMN],      g_Vil[MPAD_IMG * DIMN];

// ---------------------------- helpers ---------------------------------------
__device__ __forceinline__ uint32_t smem_u32(const void* p) {
    uint32_t a;
    asm("{ .reg .u64 t; cvta.to.shared.u64 t, %1; cvt.u32.u64 %0, t; }"
        : "=r"(a) : "l"(p));
    return a;
}

__device__ __forceinline__ void mma16816(float* d, const uint32_t* a,
                                         const uint32_t b0, const uint32_t b1) {
    asm volatile(
        "mma.sync.aligned.m16n8k16.row.col.f32.bf16.bf16.f32 "
        "{%0,%1,%2,%3}, {%4,%5,%6,%7}, {%8,%9}, {%0,%1,%2,%3};"
        : "+f"(d[0]), "+f"(d[1]), "+f"(d[2]), "+f"(d[3])
        : "r"(a[0]), "r"(a[1]), "r"(a[2]), "r"(a[3]), "r"(b0), "r"(b1));
}

__device__ __forceinline__ void ldsm4(uint32_t* r, uint32_t a) {
    asm volatile("ldmatrix.sync.aligned.m8n8.x4.shared.b16 {%0,%1,%2,%3}, [%4];"
                 : "=r"(r[0]), "=r"(r[1]), "=r"(r[2]), "=r"(r[3]) : "r"(a));
}
__device__ __forceinline__ void ldsm4t(uint32_t* r, uint32_t a) {
    asm volatile("ldmatrix.sync.aligned.m8n8.x4.trans.shared.b16 {%0,%1,%2,%3}, [%4];"
                 : "=r"(r[0]), "=r"(r[1]), "=r"(r[2]), "=r"(r[3]) : "r"(a));
}
__device__ __forceinline__ void cp16(uint32_t d, const void* s) {
    asm volatile("cp.async.cg.shared.global [%0], [%1], 16;"
                 :: "r"(d), "l"(s) : "memory");
}
__device__ __forceinline__ void cp16z(uint32_t d, const void* s, int sz) {
    asm volatile("cp.async.cg.shared.global [%0], [%1], 16, %2;"
                 :: "r"(d), "l"(s), "r"(sz) : "memory");
}
#define CP_COMMIT() asm volatile("cp.async.commit_group;" ::: "memory")
#define CP_WAIT(n)  asm volatile("cp.async.wait_group %0;" :: "n"(n) : "memory")

// f32x2 -> bf16x2 hi + lo residual
__device__ __forceinline__ void split2(float2 f, uint32_t& h, uint32_t& l) {
    __nv_bfloat162 hb = __float22bfloat162_rn(f);
    float2 hf = __bfloat1622float2(hb);
    __nv_bfloat162 lb = __float22bfloat162_rn(make_float2(f.x - hf.x, f.y - hf.y));
    h = *(uint32_t*)&hb;
    l = *(uint32_t*)&lb;
}

// -------------- batched fp32 -> bf16 hi/lo split (9 jobs, one launch) ------
struct CJob {
    const float* src;
    __nv_bfloat16 *hi, *lo;
    int Mvalid, rows_pb, bstride, roff, blk0;
};
struct CParams { CJob j[9]; };

__global__ __launch_bounds__(256)
void cvt_batch(CParams P)
{
    const int bid = blockIdx.x;
    int ji = 0;
#pragma unroll
    for (int k = 1; k < 9; k++) if (bid >= P.j[k].blk0) ji = k;
    const CJob& J = P.j[ji];

    const long e = (long)(bid - J.blk0) * 1024 + threadIdx.x * 4;
    const int m = (int)(e >> 11);
    const int col = (int)(e & 2047);

    float4 v = make_float4(0.f, 0.f, 0.f, 0.f);
    if (m < J.Mvalid) {
        const int bb = m / J.rows_pb;
        const long srow = (long)bb * J.bstride + J.roff + (m - bb * J.rows_pb);
        v = *(const float4*)(J.src + srow * DIMN + col);
    }
    uint32_t h0, l0, h1, l1;
    split2(make_float2(v.x, v.y), h0, l0);
    split2(make_float2(v.z, v.w), h1, l1);
    *(uint2*)(J.hi + e) = make_uint2(h0, h1);
    *(uint2*)(J.lo + e) = make_uint2(l0, l1);
}

// ------------- batched HMMA GEMM: C = (Ah+Al)(Bh+Bl)^T + bias (3 terms) ----
#define GT_KC 32
#define NCHUNK (DIMN / GT_KC)        /* 64 */
#define TILE_B   10240               /* 128 x 80 bytes */
#define BUF_B    (4 * TILE_B)
#define GEMM_SMEM (2 * BUF_B)

struct GJob {
    const __nv_bfloat16 *Ah, *Al, *Bh, *Bl;
    const float *bias;
    float *C;                      // fp32 out (may be null)
    __nv_bfloat16 *Ch, *Cl;        // hi/lo out (may be null)
    int Mvalid;
    int cta0;
};
struct GParams { GJob j[5]; };

__global__ __launch_bounds__(256, 2)
void gemm_batch(GParams P)
{
    extern __shared__ __nv_bfloat16 sm[];

    const int bid = blockIdx.x;
    int ji = 0;
#pragma unroll
    for (int k = 1; k < 5; k++) if (bid >= P.j[k].cta0) ji = k;
    const GJob& J = P.j[ji];
    const int local = bid - J.cta0;
    const int n0 = (local & 15) * 128;
    const int m0 = (local >> 4) * 128;

    const int tid = threadIdx.x;
    const int wid = tid >> 5;
    const int lane = tid & 31;
    const int wm = wid & 3;
    const int wn = wid >> 2;

    const __nv_bfloat16* srcs[4] = {
        J.Ah + (size_t)m0 * DIMN, J.Al + (size_t)m0 * DIMN,
        J.Bh + (size_t)n0 * DIMN, J.Bl + (size_t)n0 * DIMN };

    const uint32_t smb = smem_u32(sm);

    auto load_chunk = [&](int c, int b) {
        const int k0 = c * GT_KC;
#pragma unroll
        for (int j = 0; j < 8; j++) {
            const int f = j * 256 + tid;
            const int tile = f >> 9;
            const int w = f & 511;
            const int r = w >> 2;
            const int cc = w & 3;
            const __nv_bfloat16* sp = srcs[tile] + (size_t)r * DIMN + k0 + cc * 8;
            cp16(smb + b * BUF_B + tile * TILE_B + r * 80 + cc * 16, sp);
        }
        CP_COMMIT();
    };

    float acc[2][8][4];
#pragma unroll
    for (int i = 0; i < 2; i++)
#pragma unroll
        for (int j = 0; j < 8; j++)
#pragma unroll
            for (int q = 0; q < 4; q++) acc[i][j][q] = 0.f;

    const uint32_t aOff = (uint32_t)(wm * 32 + (lane & 15)) * 80 + ((lane >> 4) * 16);
    const uint32_t bOff = (uint32_t)(wn * 64 + (lane & 7) + ((lane >> 4) << 3)) * 80
                        + (((lane >> 3) & 1) * 16) + 2 * TILE_B;

    load_chunk(0, 0);
    load_chunk(1, 1);

    for (int c = 0; c < NCHUNK; c++) {
        const int b = c & 1;
        if (c == NCHUNK - 1) CP_WAIT(0);
        else                 CP_WAIT(1);
        __syncthreads();

        const uint32_t buf = smb + b * BUF_B;

#pragma unroll
        for (int s = 0; s < 2; s++) {
            uint32_t ah_[2][4], al_[2][4];
#pragma unroll
            for (int mt = 0; mt < 2; mt++) {
                ldsm4(ah_[mt], buf + aOff + mt * 16 * 80 + s * 32);
                ldsm4(al_[mt], buf + aOff + mt * 16 * 80 + s * 32 + TILE_B);
            }
#pragma unroll
            for (int t = 0; t < 4; t++) {
                uint32_t bh_[4], bl_[4];
                ldsm4(bh_, buf + bOff + t * 16 * 80 + s * 32);
                ldsm4(bl_, buf + bOff + t * 16 * 80 + s * 32 + TILE_B);
#pragma unroll
                for (int mt = 0; mt < 2; mt++) {
                    mma16816(acc[mt][2 * t],     ah_[mt], bh_[0], bh_[1]);
                    mma16816(acc[mt][2 * t],     ah_[mt], bl_[0], bl_[1]);
                    mma16816(acc[mt][2 * t],     al_[mt], bh_[0], bh_[1]);
                    mma16816(acc[mt][2 * t + 1], ah_[mt], bh_[2], bh_[3]);
                    mma16816(acc[mt][2 * t + 1], ah_[mt], bl_[2], bl_[3]);
                    mma16816(acc[mt][2 * t + 1], al_[mt], bh_[2], bh_[3]);
                }
            }
        }
        __syncthreads();
        if (c + 2 < NCHUNK) load_chunk(c + 2, b);
    }

    const int lr = lane >> 2;
    const int lc = (lane & 3) * 2;
#pragma unroll
    for (int mt = 0; mt < 2; mt++) {
#pragma unroll
        for (int nt = 0; nt < 8; nt++) {
            const int n = n0 + wn * 64 + nt * 8 + lc;
            const float2 bv = *(const float2*)&J.bias[n];
            const int mA = m0 + wm * 32 + mt * 16 + lr;
            float2 o0 = make_float2(acc[mt][nt][0] + bv.x, acc[mt][nt][1] + bv.y);
            float2 o1 = make_float2(acc[mt][nt][2] + bv.x, acc[mt][nt][3] + bv.y);
            if (J.C) {
                if (mA < J.Mvalid)     *(float2*)(J.C + (size_t)mA * DIMN + n) = o0;
                if (mA + 8 < J.Mvalid) *(float2*)(J.C + (size_t)(mA + 8) * DIMN + n) = o1;
            }
            if (J.Ch) {
                uint32_t hh, ll;
                if (mA < J.Mvalid) {
                    split2(o0, hh, ll);
                    *(uint32_t*)(J.Ch + (size_t)mA * DIMN + n) = hh;
                    *(uint32_t*)(J.Cl + (size_t)mA * DIMN + n) = ll;
                }
                if (mA + 8 < J.Mvalid) {
                    split2(o1, hh, ll);
                    *(uint32_t*)(J.Ch + (size_t)(mA + 8) * DIMN + n) = hh;
                    *(uint32_t*)(J.Cl + (size_t)(mA + 8) * DIMN + n) = ll;
                }
            }
        }
    }
}

// ------------- batched RMS norm -> bf16 hi/lo split (3 jobs) ---------------
struct RJob {
    const float* X;
    const float* g;
    __nv_bfloat16 *H, *L;
    int row0;
};
struct RParams { RJob j[3]; };

__global__ __launch_bounds__(256)
void rmsnorm_batch(RParams P)
{
    const int bid = blockIdx.x;
    int ji = 0;
#pragma unroll
    for (int k = 1; k < 3; k++) if (bid >= P.j[k].row0) ji = k;
    const RJob& J = P.j[ji];
    const int row = bid - J.row0;

    const float* xr = J.X + (long)row * DIMN;
    const int t = threadIdx.x;

    float4 v0 = *(const float4*)&xr[t * 4];
    float4 v1 = *(const float4*)&xr[1024 + t * 4];
    float ss = v0.x * v0.x + v0.y * v0.y + v0.z * v0.z + v0.w * v0.w
             + v1.x * v1.x + v1.y * v1.y + v1.z * v1.z + v1.w * v1.w;

#pragma unroll
    for (int o = 16; o > 0; o >>= 1) ss += __shfl_xor_sync(0xffffffffu, ss, o);

    __shared__ float red[8];
    if ((t & 31) == 0) red[t >> 5] = ss;
    __syncthreads();
    float total = 0.f;
#pragma unroll
    for (int i = 0; i < 8; i++) total += red[i];

    const float scale = rsqrtf(total * (1.0f / DIMN) + EPS_F);

    const float4 g0 = *(const float4*)&J.g[t * 4];
    const float4 g1 = *(const float4*)&J.g[1024 + t * 4];
    v0.x *= scale * g0.x; v0.y *= scale * g0.y; v0.z *= scale * g0.z; v0.w *= scale * g0.w;
    v1.x *= scale * g1.x; v1.y *= scale * g1.y; v1.z *= scale * g1.z; v1.w *= scale * g1.w;

    uint32_t h0, l0, h1, l1;
    split2(make_float2(v0.x, v0.y), h0, l0);
    split2(make_float2(v0.z, v0.w), h1, l1);
    *(uint2*)(J.H + (long)row * DIMN + t * 4) = make_uint2(h0, h1);
    *(uint2*)(J.L + (long)row * DIMN + t * 4) = make_uint2(l0, l1);
    split2(make_float2(v1.x, v1.y), h0, l0);
    split2(make_float2(v1.z, v1.w), h1, l1);
    *(uint2*)(J.H + (long)row * DIMN + 1024 + t * 4) = make_uint2(h0, h1);
    *(uint2*)(J.L + (long)row * DIMN + 1024 + t * 4) = make_uint2(l0, l1);
}

// ---------------- flash attention (img + txt), HMMA 3-term ------------------
// q-tile 128, 8 warps (16 q-rows each, full 64-key chunk width).
// Q + online stats + O register-resident; K/V double-buffered cp.async.
// chunks: 5 img (valid 257) + ceil(lens[b]/64) txt chunks (lens-trimmed).
#define KVB 34816                    /* one K or V buffer: hi 64x272 + lo */
#define OST_OFF (4 * KVB)            /* 139264 */
#define ATT_SMEM (OST_OFF + 128 * 128 * 4)   /* 204800 */

__global__ __launch_bounds__(256, 1)
void attn_kernel(const int* __restrict__ lens)
{
    extern __shared__ char smraw[];
    const uint32_t smb = smem_u32(smraw);
    float* Ost = (float*)(smraw + OST_OFF);

    const int qt = blockIdx.x, h = blockIdx.y, b = blockIdx.z;
    const int tid = threadIdx.x;
    const int wq = tid >> 5;
    const int lane = tid & 31;
    const int q0 = qt * 128;

    const int vtxt = min(lens[b], TXT_T);
    const int nch = 5 + ((vtxt + 63) >> 6);       // 9..13 chunks
    const size_t ibase = (size_t)b * IMG_T * DIMN + h * HDIM;
    const size_t tbase = (size_t)b * TXT_T * DIMN + h * HDIM;

    // ---- stage Q hi/lo into smem (KB area), then ldmatrix into regs ----
    for (int f = tid; f < 2048; f += 256) {
        const int r = f >> 4, c = f & 15;
        const size_t off = ((size_t)(b * LQ + q0 + r)) * DIMN + h * HDIM + c * 8;
        cp16(smb + r * 272 + c * 16,         g_Qh + off);
        cp16(smb + KVB + r * 272 + c * 16,   g_Ql + off);
    }
    CP_COMMIT();
    CP_WAIT(0);
    __syncthreads();

    uint32_t qh[8][4], ql[8][4];
    {
        const uint32_t aQ = smb + (uint32_t)(wq * 16 + (lane & 15)) * 272
                          + ((lane >> 4) * 16);
#pragma unroll
        for (int s8 = 0; s8 < 8; s8++) {
            ldsm4(qh[s8], aQ + s8 * 32);
            ldsm4(ql[s8], aQ + s8 * 32 + KVB);
        }
    }
    __syncthreads();

    // ---- chunk loaders ----
    auto loadK = [&](int ci) {
        if (ci < nch) {
            const __nv_bfloat16 *kh, *kl; int kbase, Lk; size_t base;
            if (ci < 5) { kh = g_Kih; kl = g_Kil; kbase = ci * 64; Lk = IMG_T; base = ibase; }
            else        { kh = g_Kth; kl = g_Ktl; kbase = (ci - 5) * 64; Lk = TXT_T; base = tbase; }
            const uint32_t dst = smb + (ci & 1) * KVB;
            for (int f = tid; f < 1024; f += 256) {
                const int r = f >> 4, cc = f & 15;
                const int kr = kbase + r;
                const int sz = (kr < Lk) ? 16 : 0;
                const int krc = (kr < Lk) ? kr : 0;
                const size_t off = base + (size_t)krc * DIMN + cc * 8;
                cp16z(dst + r * 272 + cc * 16,          kh + off, sz);
                cp16z(dst + 17408 + r * 272 + cc * 16,  kl + off, sz);
            }
        }
        CP_COMMIT();
    };
    auto loadV = [&](int ci) {
        if (ci < nch) {
            const __nv_bfloat16 *vh, *vl; int kbase, Lk; size_t base;
            if (ci < 5) { vh = g_Vih; vl = g_Vil; kbase = ci * 64; Lk = IMG_T; base = ibase; }
            else        { vh = g_Vth; vl = g_Vtl; kbase = (ci - 5) * 64; Lk = TXT_T; base = tbase; }
            const uint32_t dst = smb + 2 * KVB + (ci & 1) * KVB;
            for (int f = tid; f < 1024; f += 256) {
                const int r = f >> 4, cc = f & 15;
                const int kr = kbase + r;
                const int sz = (kr < Lk) ? 16 : 0;
                const int krc = (kr < Lk) ? kr : 0;
                const size_t off = base + (size_t)krc * DIMN + cc * 8;
                cp16z(dst + r * 272 + cc * 16,          vh + off, sz);
                cp16z(dst + 17408 + r * 272 + cc * 16,  vl + off, sz);
            }
        }
        CP_COMMIT();
    };

    float o[16][4];
#pragma unroll
    for (int i = 0; i < 16; i++)
#pragma unroll
        for (int j = 0; j < 4; j++) o[i][j] = 0.f;
    float m0 = -1e30f, m1 = -1e30f, l0 = 0.f, l1 = 0.f;

    const uint32_t kbK = (uint32_t)((lane & 7) + ((lane >> 4) << 3)) * 272
                       + (((lane >> 3) & 1) * 16);
    const uint32_t vbV = (uint32_t)(lane & 15) * 272 + ((lane >> 4) * 16);
    const int qg = lane >> 2;             // row within 16
    const int qc = 2 * (lane & 3);        // col pair base

    // pipeline prologue: K0, V0, K1
    loadK(0); loadV(0); loadK(1);

    for (int ci = 0; ci < nch; ci++) {
        const int buf = ci & 1;
        const int kbase = (ci < 5) ? ci * 64 : (ci - 5) * 64;
        const int valid = (ci < 5) ? IMG_T : vtxt;

        CP_WAIT(2);               // K(ci) ready
        __syncthreads();
        loadV(ci + 1);            // prefetch (VB[buf^1] free)

        // ---- QK scores (3-term) ----
        float s[8][4];
#pragma unroll
        for (int i = 0; i < 8; i++)
#pragma unroll
            for (int j = 0; j < 4; j++) s[i][j] = 0.f;

        const uint32_t KH = smb + buf * KVB;
#pragma unroll
        for (int s8 = 0; s8 < 8; s8++) {
#pragma unroll
            for (int t = 0; t < 4; t++) {
                uint32_t kh_[4], kl_[4];
                ldsm4(kh_, KH + kbK + t * 16 * 272 + s8 * 32);
                ldsm4(kl_, KH + kbK + t * 16 * 272 + s8 * 32 + 17408);
                mma16816(s[2 * t],     qh[s8], kh_[0], kh_[1]);
                mma16816(s[2 * t],     qh[s8], kl_[0], kl_[1]);
                mma16816(s[2 * t],     ql[s8], kh_[0], kh_[1]);
                mma16816(s[2 * t + 1], qh[s8], kh_[2], kh_[3]);
                mma16816(s[2 * t + 1], qh[s8], kl_[2], kl_[3]);
                mma16816(s[2 * t + 1], ql[s8], kh_[2], kh_[3]);
            }
        }

        // ---- online softmax (register-resident, quad reduce) ----
        float cm0 = -1e30f, cm1 = -1e30f;
#pragma unroll
        for (int nt = 0; nt < 8; nt++) {
            const int c0 = kbase + nt * 8 + qc;
#pragma unroll
            for (int j = 0; j < 2; j++) {
                const bool ok = (c0 + j) < valid;
                float t0 = ok ? s[nt][j] * ATT_SCALE : -1e30f;
                float t1 = ok ? s[nt][j + 2] * ATT_SCALE : -1e30f;
                s[nt][j] = t0; s[nt][j + 2] = t1;
                cm0 = fmaxf(cm0, t0); cm1 = fmaxf(cm1, t1);
            }
        }
        cm0 = fmaxf(cm0, __shfl_xor_sync(0xffffffffu, cm0, 1));
        cm0 = fmaxf(cm0, __shfl_xor_sync(0xffffffffu, cm0, 2));
        cm1 = fmaxf(cm1, __shfl_xor_sync(0xffffffffu, cm1, 1));
        cm1 = fmaxf(cm1, __shfl_xor_sync(0xffffffffu, cm1, 2));

        const float mn0 = fmaxf(m0, cm0), mn1 = fmaxf(m1, cm1);
        const float sc0 = __expf(m0 - mn0), sc1 = __expf(m1 - mn1);
        m0 = mn0; m1 = mn1;

        float sum0 = 0.f, sum1 = 0.f;
#pragma unroll
        for (int nt = 0; nt < 8; nt++) {
#pragma unroll
            for (int j = 0; j < 2; j++) {
                float p0 = __expf(s[nt][j] - m0);
                float p1 = __expf(s[nt][j + 2] - m1);
                s[nt][j] = p0; s[nt][j + 2] = p1;
                sum0 += p0; sum1 += p1;
            }
        }
        sum0 += __shfl_xor_sync(0xffffffffu, sum0, 1);
        sum0 += __shfl_xor_sync(0xffffffffu, sum0, 2);
        sum1 += __shfl_xor_sync(0xffffffffu, sum1, 1);
        sum1 += __shfl_xor_sync(0xffffffffu, sum1, 2);
        l0 = l0 * sc0 + sum0;
        l1 = l1 * sc1 + sum1;
#pragma unroll
        for (int nt = 0; nt < 16; nt++) {
            o[nt][0] *= sc0; o[nt][1] *= sc0;
            o[nt][2] *= sc1; o[nt][3] *= sc1;
        }

        CP_WAIT(2);               // V(ci) ready
        __syncthreads();
        loadK(ci + 2);            // prefetch (KB[buf] done)

        // ---- P @ V (3-term; P C-frags reused as A-frags) ----
        const uint32_t VH = smb + 2 * KVB + buf * KVB;
#pragma unroll
        for (int kk = 0; kk < 4; kk++) {
            uint32_t pah[4], pal[4];
            split2(make_float2(s[2 * kk][0],     s[2 * kk][1]),     pah[0], pal[0]);
            split2(make_float2(s[2 * kk][2],     s[2 * kk][3]),     pah[1], pal[1]);
            split2(make_float2(s[2 * kk + 1][0], s[2 * kk + 1][1]), pah[2], pal[2]);
            split2(make_float2(s[2 * kk + 1][2], s[2 * kk + 1][3]), pah[3], pal[3]);
            const uint32_t va = VH + vbV + kk * 16 * 272;
#pragma unroll
            for (int t = 0; t < 8; t++) {
                uint32_t vh_[4], vl_[4];
                ldsm4t(vh_, va + t * 32);
                ldsm4t(vl_, va + t * 32 + 17408);
                mma16816(o[2 * t],     pah, vh_[0], vh_[1]);
                mma16816(o[2 * t],     pah, vl_[0], vl_[1]);
                mma16816(o[2 * t],     pal, vh_[0], vh_[1]);
                mma16816(o[2 * t + 1], pah, vh_[2], vh_[3]);
                mma16816(o[2 * t + 1], pah, vl_[2], vl_[3]);
                mma16816(o[2 * t + 1], pal, vh_[2], vh_[3]);
            }
        }

        // ---- end of img phase: stash normalized output, reset stats ----
        if (ci == 4) {
            const float i0 = 1.f / l0, i1 = 1.f / l1;
            const int r0 = wq * 16 + qg;
#pragma unroll
            for (int nt = 0; nt < 16; nt++) {
                const int col = nt * 8 + qc;
                *(float2*)&Ost[r0 * 128 + col] =
                    make_float2(o[nt][0] * i0, o[nt][1] * i0);
                *(float2*)&Ost[(r0 + 8) * 128 + col] =
                    make_float2(o[nt][2] * i1, o[nt][3] * i1);
                o[nt][0] = o[nt][1] = o[nt][2] = o[nt][3] = 0.f;
            }
            m0 = m1 = -1e30f; l0 = l1 = 0.f;
        }
    }

    // ---- epilogue: out = img_stash + txt/l, write bf16 hi/lo ----
    const float i0 = 1.f / l0, i1 = 1.f / l1;
    const int r0 = wq * 16 + qg;
#pragma unroll
    for (int nt = 0; nt < 16; nt++) {
        const int col = nt * 8 + qc;
        const float2 e0 = *(const float2*)&Ost[r0 * 128 + col];
        const float2 e1 = *(const float2*)&Ost[(r0 + 8) * 128 + col];
        const int gcol = h * HDIM + col;
        const size_t a0 = (size_t)(b * LQ + q0 + r0) * DIMN + gcol;
        const size_t a1 = (size_t)(b * LQ + q0 + r0 + 8) * DIMN + gcol;
        uint32_t hh, ll;
        split2(make_float2(e0.x + o[nt][0] * i0, e0.y + o[nt][1] * i0), hh, ll);
        *(uint32_t*)&g_ah[a0] = hh;
        *(uint32_t*)&g_al[a0] = ll;
        split2(make_float2(e1.x + o[nt][2] * i1, e1.y + o[nt][3] * i1), hh, ll);
        *(uint32_t*)&g_ah[a1] = hh;
        *(uint32_t*)&g_al[a1] = ll;
    }
}

// ---------------------------- launch ---------------------------------------
extern "C" void kernel_launch(void* const* d_in, const int* in_sizes, int n_in,
                              void* d_out, int out_size)
{
    const float* x        = (const float*)d_in[0];
    const float* context  = (const float*)d_in[1];
    const int*   lens     = (const int*)  d_in[2];
    const float* w_q      = (const float*)d_in[3];
    const float* b_q      = (const float*)d_in[4];
    const float* w_k      = (const float*)d_in[5];
    const float* b_k      = (const float*)d_in[6];
    const float* w_v      = (const float*)d_in[7];
    const float* b_v      = (const float*)d_in[8];
    const float* w_k_img  = (const float*)d_in[9];
    const float* b_k_img  = (const float*)d_in[10];
    const float* w_v_img  = (const float*)d_in[11];
    const float* b_v_img  = (const float*)d_in[12];
    const float* w_o      = (const float*)d_in[13];
    const float* b_o      = (const float*)d_in[14];
    const float* g_q      = (const float*)d_in[15];
    const float* g_k      = (const float*)d_in[16];
    const float* g_k_img  = (const float*)d_in[17];
    float* out = (float*)d_out;

    float *Qb, *Ktb, *Kib;
    cudaGetSymbolAddress((void**)&Qb,  g_Q);
    cudaGetSymbolAddress((void**)&Ktb, g_Ktxt);
    cudaGetSymbolAddress((void**)&Kib, g_Kimg);

    __nv_bfloat16 *xh, *xl, *ah, *al, *cth, *ctl, *cih, *cil;
    __nv_bfloat16 *wqh, *wql, *wkh, *wkl, *wvh, *wvl, *wkih, *wkil, *wvih, *wvil, *woh, *wol;
    __nv_bfloat16 *Qhp, *Qlp, *Kthp, *Ktlp, *Vthp, *Vtlp, *Kihp, *Kilp, *Vihp, *Vilp;
    cudaGetSymbolAddress((void**)&xh,  g_xh);   cudaGetSymbolAddress((void**)&xl,  g_xl);
    cudaGetSymbolAddress((void**)&ah,  g_ah);   cudaGetSymbolAddress((void**)&al,  g_al);
    cudaGetSymbolAddress((void**)&cth, g_cth);  cudaGetSymbolAddress((void**)&ctl, g_ctl);
    cudaGetSymbolAddress((void**)&cih, g_cih);  cudaGetSymbolAddress((void**)&cil, g_cil);
    cudaGetSymbolAddress((void**)&wqh, g_wqh);  cudaGetSymbolAddress((void**)&wql, g_wql);
    cudaGetSymbolAddress((void**)&wkh, g_wkh);  cudaGetSymbolAddress((void**)&wkl, g_wkl);
    cudaGetSymbolAddress((void**)&wvh, g_wvh);  cudaGetSymbolAddress((void**)&wvl, g_wvl);
    cudaGetSymbolAddress((void**)&wkih, g_wkih); cudaGetSymbolAddress((void**)&wkil, g_wkil);
    cudaGetSymbolAddress((void**)&wvih, g_wvih); cudaGetSymbolAddress((void**)&wvil, g_wvil);
    cudaGetSymbolAddress((void**)&woh, g_woh);  cudaGetSymbolAddress((void**)&wol, g_wol);
    cudaGetSymbolAddress((void**)&Qhp, g_Qh);   cudaGetSymbolAddress((void**)&Qlp, g_Ql);
    cudaGetSymbolAddress((void**)&Kthp, g_Kth); cudaGetSymbolAddress((void**)&Ktlp, g_Ktl);
    cudaGetSymbolAddress((void**)&Vthp, g_Vth); cudaGetSymbolAddress((void**)&Vtlp, g_Vtl);
    cudaGetSymbolAddress((void**)&Kihp, g_Kih); cudaGetSymbolAddress((void**)&Kilp, g_Kil);
    cudaGetSymbolAddress((void**)&Vihp, g_Vih); cudaGetSymbolAddress((void**)&Vilp, g_Vil);

    cudaFuncSetAttribute(gemm_batch, cudaFuncAttributeMaxDynamicSharedMemorySize, GEMM_SMEM);
    cudaFuncSetAttribute(attn_kernel, cudaFuncAttributeMaxDynamicSharedMemorySize, ATT_SMEM);

    // one batched conversion launch (9 jobs)
    // blocks per job = rows * 2  (1024 elems per block)
    CParams CP;
    int blk = 0;
    auto addc = [&](const float* s, __nv_bfloat16* H, __nv_bfloat16* L,
                    int Mvalid, int Mpad, int rows_pb, int bstride, int roff, int idx) {
        CP.j[idx] = { s, H, L, Mvalid, rows_pb, bstride, roff, blk };
        blk += Mpad * 2;
    };
    addc(x,       xh,   xl,   BATCH * LQ,    BATCH * LQ,    BATCH * LQ, 0, 0, 0);
    addc(w_q,     wqh,  wql,  DIMN, DIMN, DIMN, 0, 0, 1);
    addc(w_k,     wkh,  wkl,  DIMN, DIMN, DIMN, 0, 0, 2);
    addc(w_v,     wvh,  wvl,  DIMN, DIMN, DIMN, 0, 0, 3);
    addc(w_k_img, wkih, wkil, DIMN, DIMN, DIMN, 0, 0, 4);
    addc(w_v_img, wvih, wvil, DIMN, DIMN, DIMN, 0, 0, 5);
    addc(w_o,     woh,  wol,  DIMN, DIMN, DIMN, 0, 0, 6);
    addc(context, cth,  ctl,  BATCH * TXT_T, BATCH * TXT_T, TXT_T, LCTX, IMG_T, 7);
    addc(context, cih,  cil,  BATCH * IMG_T, MPAD_IMG,      IMG_T, LCTX, 0, 8);
    cvt_batch<<<blk, 256>>>(CP);

    // batched projection GEMMs: Q, K_txt, V_txt, K_img, V_img (one launch)
    GParams P;
    P.j[0] = { xh,  xl,  wqh,  wql,  b_q,     Qb,  nullptr, nullptr, BATCH * LQ,    0    };
    P.j[1] = { cth, ctl, wkh,  wkl,  b_k,     Ktb, nullptr, nullptr, BATCH * TXT_T, 1024 };
    P.j[2] = { cth, ctl, wvh,  wvl,  b_v,     nullptr, Vthp, Vtlp,   BATCH * TXT_T, 1152 };
    P.j[3] = { cih, cil, wkih, wkil, b_k_img, Kib, nullptr, nullptr, BATCH * IMG_T, 1280 };
    P.j[4] = { cih, cil, wvih, wvil, b_v_img, nullptr, Vihp, Vilp,   BATCH * IMG_T, 1360 };
    gemm_batch<<<1440, 256, GEMM_SMEM>>>(P);

    // one batched rmsnorm+split launch (Q, K_txt, K_img)
    RParams RP;
    RP.j[0] = { Qb,  g_q,     Qhp,  Qlp,  0 };
    RP.j[1] = { Ktb, g_k,     Kthp, Ktlp, BATCH * LQ };
    RP.j[2] = { Kib, g_k_img, Kihp, Kilp, BATCH * LQ + BATCH * TXT_T };
    rmsnorm_batch<<<BATCH * LQ + BATCH * TXT_T + BATCH * IMG_T, 256>>>(RP);

    // flash attention (img + txt, lens-trimmed) -> g_ah/g_al (bf16 hi/lo)
    attn_kernel<<<dim3(LQ / 128, NHEADS, BATCH), 256, ATT_SMEM>>>(lens);

    // out = attn @ w_o^T + b_o (single-job batched kernel)
    GParams PO;
    PO.j[0] = { ah, al, woh, wol, b_o, out, nullptr, nullptr, BATCH * LQ, 0 };
    PO.j[1] = PO.j[2] = PO.j[3] = PO.j[4] = PO.j[0];
    PO.j[1].cta0 = PO.j[2].cta0 = PO.j[3].cta0 = PO.j[4].cta0 = 1 << 30;
    gemm_batch<<<1024, 256, GEMM_SMEM>>>(PO);
}